// round 9
// baseline (speedup 1.0000x reference)
#include <cuda_runtime.h>
#include <cuda_bf16.h>
#include <stdint.h>

#define TH 256
#define TM 32
#define HID 512
#define NIN 16
#define NOUT 136
#define ASTR 528            // int8 activation plane row stride (bytes)
#define NETS 137

#define XS_OFF  0                       // 32*16*4 = 2048
#define A0H_OFF 2048                    // 32*528 = 16896
#define A0L_OFF (A0H_OFF + 16896)
#define A1H_OFF (A0L_OFF + 16896)
#define A1L_OFF (A1H_OFF + 16896)
#define SMEM_BYTES (A1L_OFF + 16896)    // 69632
#define NET_OFF A0H_OFF                 // netS overlays H0 planes (free by L2 epilogue)

#define SH 8192.0f          // activation fixed-point scale (14 bit)
#define WBITS 16255.0f      // weight fixed-point target max

// fragment-ordered int8 weights: [ks][ng][lane] -> {bh0, bh1, bl0, bl1}
__device__ __align__(16) uint4 g_W1f[16 * 64 * 32];   // 512 KB
__device__ __align__(16) uint4 g_W2f[16 * 20 * 32];   // 160 KB (N padded to 160)
__device__ int g_max1bits;   // float bits of max|W1| (atomicMax on positive floats)
__device__ int g_max2bits;

// ---------------- prep 1: max reduction ----------------
__global__ void prep_max(const float* __restrict__ W1, const float* __restrict__ W2)
{
    int idx = blockIdx.x * blockDim.x + threadIdx.x;
    const int T1 = HID * HID;
    if (idx < T1) {
        float a = fabsf(W1[idx]);
        atomicMax(&g_max1bits, __float_as_int(a));
    }
    if (idx < HID * NOUT) {
        float a = fabsf(W2[idx]);
        atomicMax(&g_max2bits, __float_as_int(a));
    }
}

__device__ __forceinline__ uint32_t pack4(int b0, int b1, int b2, int b3)
{
    return (uint32_t)(uint8_t)b0 | ((uint32_t)(uint8_t)b1 << 8) |
           ((uint32_t)(uint8_t)b2 << 16) | ((uint32_t)(uint8_t)b3 << 24);
}

// ---------------- prep 2: quantize + split + fragment-order ----------------
__global__ void prep_quant(const float* __restrict__ W1, const float* __restrict__ W2)
{
    int idx = blockIdx.x * blockDim.x + threadIdx.x;
    const int T1 = 16 * 64 * 32;
    const int T2 = 16 * 20 * 32;
    const float S1 = WBITS / fmaxf(__int_as_float(g_max1bits), 1e-20f);
    const float S2 = WBITS / fmaxf(__int_as_float(g_max2bits), 1e-20f);

    if (idx < T1) {
        int lane = idx & 31, ng = (idx >> 5) & 63, ks = idx >> 11;
        int g = lane >> 2, t = lane & 3;
        int n = ng * 8 + g;
        int bh[8], bl[8];
        #pragma unroll
        for (int i = 0; i < 8; i++) {
            int k = ks * 32 + (i >> 2) * 16 + 4 * t + (i & 3);
            int q = __float2int_rn(W1[k * HID + n] * S1);
            int hi = (q + 64) >> 7;
            bh[i] = hi;
            bl[i] = q - (hi << 7);
        }
        uint4 o;
        o.x = pack4(bh[0], bh[1], bh[2], bh[3]);
        o.y = pack4(bh[4], bh[5], bh[6], bh[7]);
        o.z = pack4(bl[0], bl[1], bl[2], bl[3]);
        o.w = pack4(bl[4], bl[5], bl[6], bl[7]);
        g_W1f[idx] = o;
    } else if (idx < T1 + T2) {
        int j = idx - T1;
        int lane = j & 31, ng = (j >> 5) % 20, ks = j / (20 * 32);
        int g = lane >> 2, t = lane & 3;
        int n = ng * 8 + g;
        int bh[8], bl[8];
        #pragma unroll
        for (int i = 0; i < 8; i++) {
            int k = ks * 32 + (i >> 2) * 16 + 4 * t + (i & 3);
            float w = (n < NOUT) ? W2[k * NOUT + n] : 0.0f;
            int q = __float2int_rn(w * S2);
            int hi = (q + 64) >> 7;
            bh[i] = hi;
            bl[i] = q - (hi << 7);
        }
        uint4 o;
        o.x = pack4(bh[0], bh[1], bh[2], bh[3]);
        o.y = pack4(bh[4], bh[5], bh[6], bh[7]);
        o.z = pack4(bl[0], bl[1], bl[2], bl[3]);
        o.w = pack4(bl[4], bl[5], bl[6], bl[7]);
        g_W2f[j] = o;
    }
}

// ---------------- device helpers ----------------
__device__ __forceinline__ void imma(int* d, const uint32_t* a, uint32_t b0, uint32_t b1)
{
    asm volatile(
        "mma.sync.aligned.m16n8k32.row.col.s32.s8.s8.s32 "
        "{%0,%1,%2,%3}, {%4,%5,%6,%7}, {%8,%9}, {%0,%1,%2,%3};\n"
        : "+r"(d[0]), "+r"(d[1]), "+r"(d[2]), "+r"(d[3])
        : "r"(a[0]), "r"(a[1]), "r"(a[2]), "r"(a[3]), "r"(b0), "r"(b1));
}

__device__ __forceinline__ void ldsm4(uint32_t* r, uint32_t saddr)
{
    asm volatile("ldmatrix.sync.aligned.m8n8.x4.shared.b16 {%0,%1,%2,%3}, [%4];\n"
                 : "=r"(r[0]), "=r"(r[1]), "=r"(r[2]), "=r"(r[3])
                 : "r"(saddr));
}

__device__ __forceinline__ float ftanh(float x)
{
    float xc = fminf(fmaxf(x, -15.0f), 15.0f);
    float e  = __expf(2.0f * xc);
    return __fdividef(e - 1.0f, e + 1.0f);
}

__device__ __forceinline__ void quant_store(int8_t* ph, int8_t* pl, int idx, float h)
{
    int q  = __float2int_rn(h * SH);
    int hi = (q + 64) >> 7;
    ph[idx] = (int8_t)hi;
    pl[idx] = (int8_t)(q - (hi << 7));
}

// =====================================================================
__global__ __launch_bounds__(TH)
void ptpd_imma_kernel(const float* __restrict__ pts,
                      const float* __restrict__ W0, const float* __restrict__ b0,
                      const float* __restrict__ b1, const float* __restrict__ b2,
                      float* __restrict__ out)
{
    extern __shared__ char sm[];
    float*  Xs   = (float*)(sm + XS_OFF);
    int8_t* A0h  = (int8_t*)(sm + A0H_OFF);
    int8_t* A0l  = (int8_t*)(sm + A0L_OFF);
    int8_t* A1h  = (int8_t*)(sm + A1H_OFF);
    int8_t* A1l  = (int8_t*)(sm + A1L_OFF);
    float*  netS = (float*)(sm + NET_OFF);

    const uint32_t smb  = (uint32_t)__cvta_generic_to_shared(sm);
    const uint32_t a0hS = smb + A0H_OFF;
    const uint32_t a0lS = smb + A0L_OFF;
    const uint32_t a1hS = smb + A1H_OFF;
    const uint32_t a1lS = smb + A1L_OFF;

    const int tid  = threadIdx.x;
    const int lane = tid & 31;
    const int wid  = tid >> 5;
    const int g    = lane >> 2;
    const int t    = lane & 3;
    const long row0 = (long)blockIdx.x * TM;

    // scales
    const float S1   = WBITS / fmaxf(__int_as_float(g_max1bits), 1e-20f);
    const float S2   = WBITS / fmaxf(__int_as_float(g_max2bits), 1e-20f);
    const float inv1 = 1.0f / (SH * S1);
    const float inv2 = 1.0f / (SH * S2);

    // ldmatrix address components (16-byte half-rows)
    const int arow  = lane & 15;
    const int acol16 = (lane >> 4) << 4;

    // ---------------- X tile ----------------
    for (int i = tid; i < TM * NIN; i += TH)
        Xs[i] = pts[row0 * NIN + i];
    __syncthreads();

    // ---------------- layer 0 (scalar fp32) ----------------
    {
        const int c0 = tid, c1 = tid + 256;
        float wa[NIN], wb[NIN];
        #pragma unroll
        for (int k = 0; k < NIN; k++) {
            wa[k] = W0[k * HID + c0];
            wb[k] = W0[k * HID + c1];
        }
        const float ba = b0[c0], bb = b0[c1];
        for (int r = 0; r < TM; r++) {
            float a = ba, b = bb;
            #pragma unroll
            for (int k = 0; k < NIN; k++) {
                const float x = Xs[r * NIN + k];
                a = fmaf(x, wa[k], a);
                b = fmaf(x, wb[k], b);
            }
            quant_store(A0h, A0l, r * ASTR + c0, ftanh(a));
            quant_store(A0h, A0l, r * ASTR + c1, ftanh(b));
        }
    }
    __syncthreads();

    // =============== layer 1: 8 warps x 64 n-cols, 4 n-passes ===============
    for (int np = 0; np < 4; np++) {
        int P0[2][2][4], Pc[2][2][4], P3[2][2][4];
        #pragma unroll
        for (int mt = 0; mt < 2; mt++)
            #pragma unroll
            for (int j = 0; j < 2; j++)
                #pragma unroll
                for (int e = 0; e < 4; e++) {
                    P0[mt][j][e] = 0; Pc[mt][j][e] = 0; P3[mt][j][e] = 0;
                }

        for (int ks = 0; ks < 16; ks++) {
            uint4 bv[2];
            #pragma unroll
            for (int j = 0; j < 2; j++)
                bv[j] = g_W1f[(ks * 64 + wid * 8 + np * 2 + j) * 32 + lane];

            uint32_t ah[2][4], al[2][4];
            #pragma unroll
            for (int mt = 0; mt < 2; mt++) {
                int ro = (mt * 16 + arow) * ASTR + ks * 32 + acol16;
                ldsm4(ah[mt], a0hS + ro);
                ldsm4(al[mt], a0lS + ro);
            }

            #pragma unroll
            for (int j = 0; j < 2; j++)
                #pragma unroll
                for (int mt = 0; mt < 2; mt++)
                    imma(P0[mt][j], ah[mt], bv[j].x, bv[j].y);
            #pragma unroll
            for (int j = 0; j < 2; j++)
                #pragma unroll
                for (int mt = 0; mt < 2; mt++)
                    imma(Pc[mt][j], ah[mt], bv[j].z, bv[j].w);
            #pragma unroll
            for (int j = 0; j < 2; j++)
                #pragma unroll
                for (int mt = 0; mt < 2; mt++)
                    imma(Pc[mt][j], al[mt], bv[j].x, bv[j].y);
            #pragma unroll
            for (int j = 0; j < 2; j++)
                #pragma unroll
                for (int mt = 0; mt < 2; mt++)
                    imma(P3[mt][j], al[mt], bv[j].z, bv[j].w);
        }

        // combine -> tanh -> quantize -> H1 planes
        const float k14 = 16384.0f * inv1;
        const float k7  = 128.0f * inv1;
        #pragma unroll
        for (int mt = 0; mt < 2; mt++)
            #pragma unroll
            for (int j = 0; j < 2; j++) {
                int colb = wid * 64 + np * 16 + j * 8 + 2 * t;
                #pragma unroll
                for (int e = 0; e < 4; e++) {
                    int r   = mt * 16 + g + (e >> 1) * 8;
                    int col = colb + (e & 1);
                    float z = fmaf((float)P0[mt][j][e], k14,
                              fmaf((float)Pc[mt][j][e], k7,
                                   (float)P3[mt][j][e] * inv1)) + b1[col];
                    quant_store(A1h, A1l, r * ASTR + col, ftanh(z));
                }
            }
    }
    __syncthreads();

    // =============== layer 2: 2 m-warps x 4 n-warps (N padded 160) ===============
    {
        const int wm = wid & 1;      // 16 rows
        const int wn = wid >> 1;     // 40 cols (5 n-groups)
        int P0[5][4], Pc[5][4], P3[5][4];
        #pragma unroll
        for (int j = 0; j < 5; j++)
            #pragma unroll
            for (int e = 0; e < 4; e++) { P0[j][e] = 0; Pc[j][e] = 0; P3[j][e] = 0; }

        for (int ks = 0; ks < 16; ks++) {
            uint4 bv[5];
            #pragma unroll
            for (int j = 0; j < 5; j++)
                bv[j] = g_W2f[(ks * 20 + wn * 5 + j) * 32 + lane];

            uint32_t ah[4], al[4];
            int ro = (wm * 16 + arow) * ASTR + ks * 32 + acol16;
            ldsm4(ah, a1hS + ro);
            ldsm4(al, a1lS + ro);

            #pragma unroll
            for (int j = 0; j < 5; j++) imma(P0[j], ah, bv[j].x, bv[j].y);
            #pragma unroll
            for (int j = 0; j < 5; j++) imma(Pc[j], ah, bv[j].z, bv[j].w);
            #pragma unroll
            for (int j = 0; j < 5; j++) imma(Pc[j], al, bv[j].x, bv[j].y);
            #pragma unroll
            for (int j = 0; j < 5; j++) imma(P3[j], al, bv[j].z, bv[j].w);
        }

        __syncthreads();   // H0 planes fully consumed (L1 done) -> netS overlay safe

        const float k14 = 16384.0f * inv2;
        const float k7  = 128.0f * inv2;
        #pragma unroll
        for (int j = 0; j < 5; j++) {
            int colb = wn * 40 + j * 8 + 2 * t;
            #pragma unroll
            for (int e = 0; e < 4; e++) {
                int r   = wm * 16 + g + (e >> 1) * 8;
                int col = colb + (e & 1);
                if (col < NOUT) {
                    float z = fmaf((float)P0[j][e], k14,
                              fmaf((float)Pc[j][e], k7,
                                   (float)P3[j][e] * inv2)) + b2[col];
                    netS[r * NETS + col] = z;
                }
            }
        }
    }
    __syncthreads();

    // ---------------- quadratic form ----------------
    if (tid < TM) {
        const float* nn = netS + tid * NETS;
        const float* xv = Xs + tid * NIN;
        float x[NIN], sx = 0.0f;
        #pragma unroll
        for (int i = 0; i < NIN; i++) { x[i] = xv[i]; sx = fmaf(x[i], x[i], sx); }
        float y[NIN];
        #pragma unroll
        for (int j = 0; j < NIN; j++) y[j] = 0.0f;
        int tt = 0;
        #pragma unroll
        for (int i = 0; i < NIN; i++) {
            #pragma unroll
            for (int j = 0; j <= i; j++) {
                y[j] = fmaf(nn[tt], x[i], y[j]);
                tt++;
            }
        }
        float v = 0.0f;
        #pragma unroll
        for (int j = 0; j < NIN; j++) v = fmaf(y[j], y[j], v);
        out[row0 + tid] = v + 1e-6f * sx;
    }
}

extern "C" void kernel_launch(void* const* d_in, const int* in_sizes, int n_in,
                              void* d_out, int out_size)
{
    const float* pts = (const float*)d_in[0];
    const float* W0  = (const float*)d_in[1];
    const float* b0  = (const float*)d_in[2];
    const float* W1  = (const float*)d_in[3];
    const float* b1  = (const float*)d_in[4];
    const float* W2  = (const float*)d_in[5];
    const float* b2  = (const float*)d_in[6];
    float* out = (float*)d_out;

    const int B = in_sizes[0] / NIN;

    cudaFuncSetAttribute(ptpd_imma_kernel,
                         cudaFuncAttributeMaxDynamicSharedMemorySize, SMEM_BYTES);

    prep_max<<<(HID * HID + 255) / 256, 256>>>(W1, W2);
    const int qthreads = 16 * 64 * 32 + 16 * 20 * 32;
    prep_quant<<<(qthreads + 255) / 256, 256>>>(W1, W2);

    ptpd_imma_kernel<<<B / TM, TH, SMEM_BYTES>>>(pts, W0, b0, b1, b2, out);
}

// round 10
// speedup vs baseline: 3.4827x; 3.4827x over previous
#include <cuda_runtime.h>
#include <cuda_bf16.h>
#include <stdint.h>

#define TH 256
#define TM 32
#define HID 512
#define NIN 16
#define NOUT 136
#define HS 520              // H row stride (bf16): conflict-free for ldmatrix
#define NETS 137

#define XS_OFF  0                        // 32*16*4 = 2048
#define HH_OFF  2048                     // 32*520*2 = 33280
#define HL_OFF  (HH_OFF + 33280)
#define SMEM_BYTES (HL_OFF + 33280)      // 68608
#define NET_OFF HH_OFF                   // netS overlays Hh (free after L2 MMAs)

// fragment-ordered weights: [ks][ng][lane] -> {bhi0, bhi1, blo0, blo1}
__device__ __align__(16) uint4 g_W1f[32 * 64 * 32];   // 1 MB
__device__ __align__(16) uint4 g_W2f[32 * 20 * 32];   // 320 KB (N padded to 160)

__device__ __forceinline__ uint32_t pack_bf2(float a, float b)
{
    __nv_bfloat162 p = __floats2bfloat162_rn(a, b);
    return *(uint32_t*)&p;
}

__device__ __forceinline__ uint4 make_frag(float v00, float v01, float v10, float v11)
{
    float h00 = __bfloat162float(__float2bfloat16(v00));
    float h01 = __bfloat162float(__float2bfloat16(v01));
    float h10 = __bfloat162float(__float2bfloat16(v10));
    float h11 = __bfloat162float(__float2bfloat16(v11));
    uint4 o;
    o.x = pack_bf2(h00, h01);
    o.y = pack_bf2(h10, h11);
    o.z = pack_bf2(v00 - h00, v01 - h01);
    o.w = pack_bf2(v10 - h10, v11 - h11);
    return o;
}

__global__ void prep_weights(const float* __restrict__ W1,
                             const float* __restrict__ W2)
{
    int idx = blockIdx.x * blockDim.x + threadIdx.x;
    const int T1 = 32 * 64 * 32;
    const int T2 = 32 * 20 * 32;
    if (idx < T1) {
        int lane = idx & 31, ng = (idx >> 5) & 63, ks = idx >> 11;
        int g = lane >> 2, t = lane & 3;
        int n = ng * 8 + g;
        int k0 = ks * 16 + 2 * t;
        g_W1f[idx] = make_frag(W1[(k0    )*HID + n], W1[(k0 + 1)*HID + n],
                               W1[(k0 + 8)*HID + n], W1[(k0 + 9)*HID + n]);
    } else if (idx < T1 + T2) {
        int j = idx - T1;
        int lane = j & 31, ng = (j >> 5) % 20, ks = j / (20 * 32);
        int g = lane >> 2, t = lane & 3;
        int n = ng * 8 + g;
        int k0 = ks * 16 + 2 * t;
        float v00 = (n < NOUT) ? W2[(k0    )*NOUT + n] : 0.0f;
        float v01 = (n < NOUT) ? W2[(k0 + 1)*NOUT + n] : 0.0f;
        float v10 = (n < NOUT) ? W2[(k0 + 8)*NOUT + n] : 0.0f;
        float v11 = (n < NOUT) ? W2[(k0 + 9)*NOUT + n] : 0.0f;
        g_W2f[j] = make_frag(v00, v01, v10, v11);
    }
}

__device__ __forceinline__ void mma16816(float* d, const uint32_t* a,
                                         uint32_t b0, uint32_t b1)
{
    asm volatile(
        "mma.sync.aligned.m16n8k16.row.col.f32.bf16.bf16.f32 "
        "{%0,%1,%2,%3}, {%4,%5,%6,%7}, {%8,%9}, {%0,%1,%2,%3};\n"
        : "+f"(d[0]), "+f"(d[1]), "+f"(d[2]), "+f"(d[3])
        : "r"(a[0]), "r"(a[1]), "r"(a[2]), "r"(a[3]),
          "r"(b0), "r"(b1));
}

__device__ __forceinline__ void ldsm4(uint32_t* r, uint32_t saddr)
{
    asm volatile("ldmatrix.sync.aligned.m8n8.x4.shared.b16 {%0,%1,%2,%3}, [%4];\n"
                 : "=r"(r[0]), "=r"(r[1]), "=r"(r[2]), "=r"(r[3])
                 : "r"(saddr));
}

__device__ __forceinline__ float ftanh(float x)
{
    float xc = fminf(fmaxf(x, -15.0f), 15.0f);
    float e  = __expf(2.0f * xc);
    return __fdividef(e - 1.0f, e + 1.0f);
}

__device__ __forceinline__ void split_store2(__nv_bfloat16* Hh, __nv_bfloat16* Hl,
                                             int idx, float v0, float v1)
{
    __nv_bfloat162 hp = __floats2bfloat162_rn(v0, v1);
    float r0 = v0 - __bfloat162float(hp.x);
    float r1 = v1 - __bfloat162float(hp.y);
    __nv_bfloat162 lp = __floats2bfloat162_rn(r0, r1);
    *(__nv_bfloat162*)(Hh + idx) = hp;
    *(__nv_bfloat162*)(Hl + idx) = lp;
}

__global__ __launch_bounds__(TH, 2)
void ptpd_mma_kernel(const float* __restrict__ pts,
                     const float* __restrict__ W0, const float* __restrict__ b0,
                     const float* __restrict__ b1, const float* __restrict__ b2,
                     float* __restrict__ out)
{
    extern __shared__ char sm[];
    float*          Xs  = (float*)(sm + XS_OFF);
    __nv_bfloat16*  Hh  = (__nv_bfloat16*)(sm + HH_OFF);
    __nv_bfloat16*  Hl  = (__nv_bfloat16*)(sm + HL_OFF);
    float*          netS = (float*)(sm + NET_OFF);   // overlays Hh after L2 MMAs

    const uint32_t smb = (uint32_t)__cvta_generic_to_shared(sm);
    const uint32_t hhS = smb + HH_OFF;
    const uint32_t hlS = smb + HL_OFF;

    const int tid  = threadIdx.x;
    const int lane = tid & 31;
    const int wid  = tid >> 5;
    const int g    = lane >> 2;
    const int t    = lane & 3;
    const long row0 = (long)blockIdx.x * TM;

    const int arow  = lane & 15;
    const int acol8 = (lane >> 4) << 3;

    // ---------------- X tile ----------------
    for (int i = tid; i < TM*NIN; i += TH)
        Xs[i] = pts[row0*NIN + i];
    __syncthreads();

    // ---------------- layer 0 (scalar; 2 cols/thread, 32 rows) ----------------
    {
        const int c0 = tid, c1 = tid + 256;
        float w0a[NIN], w0b[NIN];
        #pragma unroll
        for (int k = 0; k < NIN; k++) {
            w0a[k] = W0[k*HID + c0];
            w0b[k] = W0[k*HID + c1];
        }
        const float ba = b0[c0], bb = b0[c1];
        for (int r = 0; r < TM; r++) {
            float a = ba, b = bb;
            #pragma unroll
            for (int k = 0; k < NIN; k++) {
                const float x = Xs[r*NIN + k];
                a = fmaf(x, w0a[k], a);
                b = fmaf(x, w0b[k], b);
            }
            a = ftanh(a); b = ftanh(b);
            __nv_bfloat16 ah = __float2bfloat16(a);
            Hh[r*HS + c0] = ah;
            Hl[r*HS + c0] = __float2bfloat16(a - __bfloat162float(ah));
            __nv_bfloat16 bh = __float2bfloat16(b);
            Hh[r*HS + c1] = bh;
            Hl[r*HS + c1] = __float2bfloat16(b - __bfloat162float(bh));
        }
    }
    __syncthreads();

    // =============== layer 1: each warp owns 64 n-cols, 32 rows ===============
    {
        float acc1[2][8][4];
        #pragma unroll
        for (int nt = 0; nt < 8; nt++) {
            int col = wid*64 + nt*8 + 2*t;
            float bv0 = b1[col], bv1 = b1[col + 1];
            #pragma unroll
            for (int mt = 0; mt < 2; mt++) {
                acc1[mt][nt][0] = bv0; acc1[mt][nt][1] = bv1;
                acc1[mt][nt][2] = bv0; acc1[mt][nt][3] = bv1;
            }
        }

        for (int ks = 0; ks < 32; ks++) {
            uint4 bv[8];
            #pragma unroll
            for (int nt = 0; nt < 8; nt++)
                bv[nt] = g_W1f[(ks*64 + wid*8 + nt)*32 + lane];

            uint32_t ah[2][4], al[2][4];
            #pragma unroll
            for (int mt = 0; mt < 2; mt++) {
                int ro = (mt*16 + arow)*HS + ks*16 + acol8;
                ldsm4(ah[mt], hhS + ro*2);
                ldsm4(al[mt], hlS + ro*2);
            }

            #pragma unroll
            for (int nt = 0; nt < 8; nt++)
                #pragma unroll
                for (int mt = 0; mt < 2; mt++) {
                    mma16816(acc1[mt][nt], ah[mt], bv[nt].x, bv[nt].y);
                    mma16816(acc1[mt][nt], ah[mt], bv[nt].z, bv[nt].w);
                    mma16816(acc1[mt][nt], al[mt], bv[nt].x, bv[nt].y);
                }
        }

        __syncthreads();    // all warps done READING H0 before overwrite

        // tanh + split -> H1 (overwrites H0 buffers)
        #pragma unroll
        for (int mt = 0; mt < 2; mt++)
            #pragma unroll
            for (int nt = 0; nt < 8; nt++) {
                int r   = mt*16 + g;
                int col = wid*64 + nt*8 + 2*t;
                split_store2(Hh, Hl, r*HS + col,
                             ftanh(acc1[mt][nt][0]), ftanh(acc1[mt][nt][1]));
                split_store2(Hh, Hl, (r + 8)*HS + col,
                             ftanh(acc1[mt][nt][2]), ftanh(acc1[mt][nt][3]));
            }
    }
    __syncthreads();

    // =============== layer 2: 2 m-warps x 4 n-warps (N padded 160) ===============
    {
        const int wm = wid & 1;      // 16 rows each
        const int wn = wid >> 1;     // 40 cols (5 n-tiles)
        float acc2[5][4];
        #pragma unroll
        for (int nt = 0; nt < 5; nt++) {
            int col = wn*40 + nt*8 + 2*t;
            float bv0 = (col     < NOUT) ? b2[col]     : 0.0f;
            float bv1 = (col + 1 < NOUT) ? b2[col + 1] : 0.0f;
            acc2[nt][0] = bv0; acc2[nt][1] = bv1;
            acc2[nt][2] = bv0; acc2[nt][3] = bv1;
        }

        for (int ks = 0; ks < 32; ks++) {
            uint4 bv[5];
            #pragma unroll
            for (int nt = 0; nt < 5; nt++)
                bv[nt] = g_W2f[(ks*20 + wn*5 + nt)*32 + lane];

            uint32_t ah[4], al[4];
            int ro = (wm*16 + arow)*HS + ks*16 + acol8;
            ldsm4(ah, hhS + ro*2);
            ldsm4(al, hlS + ro*2);

            #pragma unroll
            for (int nt = 0; nt < 5; nt++) {
                mma16816(acc2[nt], ah, bv[nt].x, bv[nt].y);
                mma16816(acc2[nt], ah, bv[nt].z, bv[nt].w);
                mma16816(acc2[nt], al, bv[nt].x, bv[nt].y);
            }
        }

        __syncthreads();   // all warps done READING H1 -> netS overlay safe

        // net -> smem (overlays Hh)
        #pragma unroll
        for (int nt = 0; nt < 5; nt++) {
            int r   = wm*16 + g;
            int col = wn*40 + nt*8 + 2*t;
            if (col + 1 < NOUT) {
                netS[r*NETS + col]           = acc2[nt][0];
                netS[r*NETS + col + 1]       = acc2[nt][1];
                netS[(r + 8)*NETS + col]     = acc2[nt][2];
                netS[(r + 8)*NETS + col + 1] = acc2[nt][3];
            }
        }
    }
    __syncthreads();

    // ---------------- quadratic form ----------------
    if (tid < TM) {
        const float* nn = netS + tid*NETS;
        const float* xv = Xs + tid*NIN;
        float x[NIN], sx = 0.0f;
        #pragma unroll
        for (int i = 0; i < NIN; i++) { x[i] = xv[i]; sx = fmaf(x[i], x[i], sx); }
        float y[NIN];
        #pragma unroll
        for (int j = 0; j < NIN; j++) y[j] = 0.0f;
        int tt = 0;
        #pragma unroll
        for (int i = 0; i < NIN; i++) {
            #pragma unroll
            for (int j = 0; j <= i; j++) {
                y[j] = fmaf(nn[tt], x[i], y[j]);
                tt++;
            }
        }
        float v = 0.0f;
        #pragma unroll
        for (int j = 0; j < NIN; j++) v = fmaf(y[j], y[j], v);
        out[row0 + tid] = v + 1e-6f * sx;
    }
}

extern "C" void kernel_launch(void* const* d_in, const int* in_sizes, int n_in,
                              void* d_out, int out_size)
{
    const float* pts = (const float*)d_in[0];
    const float* W0  = (const float*)d_in[1];
    const float* b0  = (const float*)d_in[2];
    const float* W1  = (const float*)d_in[3];
    const float* b1  = (const float*)d_in[4];
    const float* W2  = (const float*)d_in[5];
    const float* b2  = (const float*)d_in[6];
    float* out = (float*)d_out;

    const int B = in_sizes[0] / NIN;

    cudaFuncSetAttribute(ptpd_mma_kernel,
                         cudaFuncAttributeMaxDynamicSharedMemorySize, SMEM_BYTES);

    const int prep_threads = 32*64*32 + 32*20*32;
    prep_weights<<<(prep_threads + 255)/256, 256>>>(W1, W2);

    ptpd_mma_kernel<<<B/TM, TH, SMEM_BYTES>>>(pts, W0, b0, b1, b2, out);
}

// round 11
// speedup vs baseline: 3.6843x; 1.0579x over previous
#include <cuda_runtime.h>
#include <cuda_bf16.h>
#include <stdint.h>

#define TH 256
#define TM 32
#define HID 512
#define NIN 16
#define NOUT 136
#define HS 520              // H row stride (bf16): conflict-free for ldmatrix
#define XSTR 24             // X hi/lo row stride (bf16): 48B rows, conflict-free
#define NETS 137

#define XS_OFF  0                        // 32*16*4 = 2048
#define XH_OFF  2048                     // 32*24*2 = 1536
#define XL_OFF  (XH_OFF + 1536)
#define HH_OFF  (XL_OFF + 1536)          // 5120
#define HL_OFF  (HH_OFF + 33280)
#define SMEM_BYTES (HL_OFF + 33280)      // 71680
#define NET_OFF HH_OFF                   // netS overlays Hh (free after L2 MMAs)

// fragment-ordered weights: [ks][ng][lane] -> {bhi0, bhi1, blo0, blo1}
__device__ __align__(16) uint4 g_W0f[64 * 32];        // 32 KB (single k-step)
__device__ __align__(16) uint4 g_W1f[32 * 64 * 32];   // 1 MB
__device__ __align__(16) uint4 g_W2f[32 * 20 * 32];   // 320 KB (N padded to 160)

__device__ __forceinline__ uint32_t pack_bf2(float a, float b)
{
    __nv_bfloat162 p = __floats2bfloat162_rn(a, b);
    return *(uint32_t*)&p;
}

__device__ __forceinline__ uint4 make_frag(float v00, float v01, float v10, float v11)
{
    float h00 = __bfloat162float(__float2bfloat16(v00));
    float h01 = __bfloat162float(__float2bfloat16(v01));
    float h10 = __bfloat162float(__float2bfloat16(v10));
    float h11 = __bfloat162float(__float2bfloat16(v11));
    uint4 o;
    o.x = pack_bf2(h00, h01);
    o.y = pack_bf2(h10, h11);
    o.z = pack_bf2(v00 - h00, v01 - h01);
    o.w = pack_bf2(v10 - h10, v11 - h11);
    return o;
}

__global__ void prep_weights(const float* __restrict__ W0,
                             const float* __restrict__ W1,
                             const float* __restrict__ W2)
{
    int idx = blockIdx.x * blockDim.x + threadIdx.x;
    const int T0 = 64 * 32;
    const int T1 = 32 * 64 * 32;
    const int T2 = 32 * 20 * 32;
    if (idx < T0) {
        int lane = idx & 31, ng = idx >> 5;
        int g = lane >> 2, t = lane & 3;
        int n = ng * 8 + g;
        int k0 = 2 * t;
        g_W0f[idx] = make_frag(W0[(k0    )*HID + n], W0[(k0 + 1)*HID + n],
                               W0[(k0 + 8)*HID + n], W0[(k0 + 9)*HID + n]);
    } else if (idx < T0 + T1) {
        int i = idx - T0;
        int lane = i & 31, ng = (i >> 5) & 63, ks = i >> 11;
        int g = lane >> 2, t = lane & 3;
        int n = ng * 8 + g;
        int k0 = ks * 16 + 2 * t;
        g_W1f[i] = make_frag(W1[(k0    )*HID + n], W1[(k0 + 1)*HID + n],
                             W1[(k0 + 8)*HID + n], W1[(k0 + 9)*HID + n]);
    } else if (idx < T0 + T1 + T2) {
        int j = idx - T0 - T1;
        int lane = j & 31, ng = (j >> 5) % 20, ks = j / (20 * 32);
        int g = lane >> 2, t = lane & 3;
        int n = ng * 8 + g;
        int k0 = ks * 16 + 2 * t;
        float v00 = (n < NOUT) ? W2[(k0    )*NOUT + n] : 0.0f;
        float v01 = (n < NOUT) ? W2[(k0 + 1)*NOUT + n] : 0.0f;
        float v10 = (n < NOUT) ? W2[(k0 + 8)*NOUT + n] : 0.0f;
        float v11 = (n < NOUT) ? W2[(k0 + 9)*NOUT + n] : 0.0f;
        g_W2f[j] = make_frag(v00, v01, v10, v11);
    }
}

__device__ __forceinline__ void mma16816(float* d, const uint32_t* a,
                                         uint32_t b0, uint32_t b1)
{
    asm volatile(
        "mma.sync.aligned.m16n8k16.row.col.f32.bf16.bf16.f32 "
        "{%0,%1,%2,%3}, {%4,%5,%6,%7}, {%8,%9}, {%0,%1,%2,%3};\n"
        : "+f"(d[0]), "+f"(d[1]), "+f"(d[2]), "+f"(d[3])
        : "r"(a[0]), "r"(a[1]), "r"(a[2]), "r"(a[3]),
          "r"(b0), "r"(b1));
}

__device__ __forceinline__ void ldsm4(uint32_t* r, uint32_t saddr)
{
    asm volatile("ldmatrix.sync.aligned.m8n8.x4.shared.b16 {%0,%1,%2,%3}, [%4];\n"
                 : "=r"(r[0]), "=r"(r[1]), "=r"(r[2]), "=r"(r[3])
                 : "r"(saddr));
}

__device__ __forceinline__ float ftanh(float x)
{
    float xc = fminf(fmaxf(x, -15.0f), 15.0f);
    float e  = __expf(2.0f * xc);
    return __fdividef(e - 1.0f, e + 1.0f);
}

__device__ __forceinline__ void split_store2(__nv_bfloat16* Hh, __nv_bfloat16* Hl,
                                             int idx, float v0, float v1)
{
    __nv_bfloat162 hp = __floats2bfloat162_rn(v0, v1);
    float r0 = v0 - __bfloat162float(hp.x);
    float r1 = v1 - __bfloat162float(hp.y);
    __nv_bfloat162 lp = __floats2bfloat162_rn(r0, r1);
    *(__nv_bfloat162*)(Hh + idx) = hp;
    *(__nv_bfloat162*)(Hl + idx) = lp;
}

__global__ __launch_bounds__(TH, 2)
void ptpd_mma_kernel(const float* __restrict__ pts,
                     const float* __restrict__ b0,
                     const float* __restrict__ b1, const float* __restrict__ b2,
                     float* __restrict__ out)
{
    extern __shared__ char sm[];
    float*          Xs  = (float*)(sm + XS_OFF);
    __nv_bfloat16*  Xh  = (__nv_bfloat16*)(sm + XH_OFF);
    __nv_bfloat16*  Xl  = (__nv_bfloat16*)(sm + XL_OFF);
    __nv_bfloat16*  Hh  = (__nv_bfloat16*)(sm + HH_OFF);
    __nv_bfloat16*  Hl  = (__nv_bfloat16*)(sm + HL_OFF);
    float*          netS = (float*)(sm + NET_OFF);   // overlays Hh after L2 MMAs

    const uint32_t smb = (uint32_t)__cvta_generic_to_shared(sm);
    const uint32_t xhS = smb + XH_OFF;
    const uint32_t xlS = smb + XL_OFF;
    const uint32_t hhS = smb + HH_OFF;
    const uint32_t hlS = smb + HL_OFF;

    const int tid  = threadIdx.x;
    const int lane = tid & 31;
    const int wid  = tid >> 5;
    const int g    = lane >> 2;
    const int t    = lane & 3;
    const long row0 = (long)blockIdx.x * TM;

    const int arow  = lane & 15;
    const int acol8 = (lane >> 4) << 3;

    // ---------------- X tile: fp32 + hi/lo split ----------------
    for (int i = tid; i < TM*NIN; i += TH) {
        float x = pts[row0*NIN + i];
        Xs[i] = x;
        int r = i >> 4, c = i & 15;
        __nv_bfloat16 xh = __float2bfloat16(x);
        Xh[r*XSTR + c] = xh;
        Xl[r*XSTR + c] = __float2bfloat16(x - __bfloat162float(xh));
    }
    __syncthreads();

    // ---------------- layer 0 via MMA (K=16, 1 k-step) ----------------
    {
        float acc0[2][8][4];
        #pragma unroll
        for (int nt = 0; nt < 8; nt++) {
            int col = wid*64 + nt*8 + 2*t;
            float bv0 = b0[col], bv1 = b0[col + 1];
            #pragma unroll
            for (int mt = 0; mt < 2; mt++) {
                acc0[mt][nt][0] = bv0; acc0[mt][nt][1] = bv1;
                acc0[mt][nt][2] = bv0; acc0[mt][nt][3] = bv1;
            }
        }
        uint32_t xhf[2][4], xlf[2][4];
        #pragma unroll
        for (int mt = 0; mt < 2; mt++) {
            int ro = (mt*16 + arow)*XSTR + acol8;
            ldsm4(xhf[mt], xhS + ro*2);
            ldsm4(xlf[mt], xlS + ro*2);
        }
        // n-tiles in 2 halves of 4 (caps live registers)
        #pragma unroll
        for (int h = 0; h < 2; h++) {
            uint4 bv[4];
            #pragma unroll
            for (int j = 0; j < 4; j++)
                bv[j] = g_W0f[(wid*8 + h*4 + j)*32 + lane];
            #pragma unroll
            for (int j = 0; j < 4; j++)
                #pragma unroll
                for (int mt = 0; mt < 2; mt++) {
                    mma16816(acc0[mt][h*4 + j], xhf[mt], bv[j].x, bv[j].y);
                    mma16816(acc0[mt][h*4 + j], xhf[mt], bv[j].z, bv[j].w);
                    mma16816(acc0[mt][h*4 + j], xlf[mt], bv[j].x, bv[j].y);
                }
        }
        // tanh + split -> H0
        #pragma unroll
        for (int mt = 0; mt < 2; mt++)
            #pragma unroll
            for (int nt = 0; nt < 8; nt++) {
                int r   = mt*16 + g;
                int col = wid*64 + nt*8 + 2*t;
                split_store2(Hh, Hl, r*HS + col,
                             ftanh(acc0[mt][nt][0]), ftanh(acc0[mt][nt][1]));
                split_store2(Hh, Hl, (r + 8)*HS + col,
                             ftanh(acc0[mt][nt][2]), ftanh(acc0[mt][nt][3]));
            }
    }
    __syncthreads();

    // =============== layer 1: each warp owns 64 n-cols, 32 rows ===============
    {
        float acc1[2][8][4];
        #pragma unroll
        for (int nt = 0; nt < 8; nt++) {
            int col = wid*64 + nt*8 + 2*t;
            float bv0 = b1[col], bv1 = b1[col + 1];
            #pragma unroll
            for (int mt = 0; mt < 2; mt++) {
                acc1[mt][nt][0] = bv0; acc1[mt][nt][1] = bv1;
                acc1[mt][nt][2] = bv0; acc1[mt][nt][3] = bv1;
            }
        }

        for (int ks = 0; ks < 32; ks++) {
            uint4 bv[8];
            #pragma unroll
            for (int nt = 0; nt < 8; nt++)
                bv[nt] = g_W1f[(ks*64 + wid*8 + nt)*32 + lane];

            uint32_t ah[2][4], al[2][4];
            #pragma unroll
            for (int mt = 0; mt < 2; mt++) {
                int ro = (mt*16 + arow)*HS + ks*16 + acol8;
                ldsm4(ah[mt], hhS + ro*2);
                ldsm4(al[mt], hlS + ro*2);
            }

            #pragma unroll
            for (int nt = 0; nt < 8; nt++)
                #pragma unroll
                for (int mt = 0; mt < 2; mt++) {
                    mma16816(acc1[mt][nt], ah[mt], bv[nt].x, bv[nt].y);
                    mma16816(acc1[mt][nt], ah[mt], bv[nt].z, bv[nt].w);
                    mma16816(acc1[mt][nt], al[mt], bv[nt].x, bv[nt].y);
                }
        }

        __syncthreads();    // all warps done READING H0 before overwrite

        // tanh + split -> H1 (overwrites H0 buffers)
        #pragma unroll
        for (int mt = 0; mt < 2; mt++)
            #pragma unroll
            for (int nt = 0; nt < 8; nt++) {
                int r   = mt*16 + g;
                int col = wid*64 + nt*8 + 2*t;
                split_store2(Hh, Hl, r*HS + col,
                             ftanh(acc1[mt][nt][0]), ftanh(acc1[mt][nt][1]));
                split_store2(Hh, Hl, (r + 8)*HS + col,
                             ftanh(acc1[mt][nt][2]), ftanh(acc1[mt][nt][3]));
            }
    }
    __syncthreads();

    // =============== layer 2: 2 m-warps x 4 n-warps (N padded 160) ===============
    {
        const int wm = wid & 1;      // 16 rows each
        const int wn = wid >> 1;     // 40 cols (5 n-tiles)
        float acc2[5][4];
        #pragma unroll
        for (int nt = 0; nt < 5; nt++) {
            int col = wn*40 + nt*8 + 2*t;
            float bv0 = (col     < NOUT) ? b2[col]     : 0.0f;
            float bv1 = (col + 1 < NOUT) ? b2[col + 1] : 0.0f;
            acc2[nt][0] = bv0; acc2[nt][1] = bv1;
            acc2[nt][2] = bv0; acc2[nt][3] = bv1;
        }

        for (int ks = 0; ks < 32; ks++) {
            uint4 bv[5];
            #pragma unroll
            for (int nt = 0; nt < 5; nt++)
                bv[nt] = g_W2f[(ks*20 + wn*5 + nt)*32 + lane];

            uint32_t ah[4], al[4];
            int ro = (wm*16 + arow)*HS + ks*16 + acol8;
            ldsm4(ah, hhS + ro*2);
            ldsm4(al, hlS + ro*2);

            #pragma unroll
            for (int nt = 0; nt < 5; nt++) {
                mma16816(acc2[nt], ah, bv[nt].x, bv[nt].y);
                mma16816(acc2[nt], ah, bv[nt].z, bv[nt].w);
                mma16816(acc2[nt], al, bv[nt].x, bv[nt].y);
            }
        }

        __syncthreads();   // all warps done READING H1 -> netS overlay safe

        // net -> smem (overlays Hh)
        #pragma unroll
        for (int nt = 0; nt < 5; nt++) {
            int r   = wm*16 + g;
            int col = wn*40 + nt*8 + 2*t;
            if (col + 1 < NOUT) {
                netS[r*NETS + col]           = acc2[nt][0];
                netS[r*NETS + col + 1]       = acc2[nt][1];
                netS[(r + 8)*NETS + col]     = acc2[nt][2];
                netS[(r + 8)*NETS + col + 1] = acc2[nt][3];
            }
        }
    }
    __syncthreads();

    // ---------------- quadratic form ----------------
    if (tid < TM) {
        const float* nn = netS + tid*NETS;
        const float* xv = Xs + tid*NIN;
        float x[NIN], sx = 0.0f;
        #pragma unroll
        for (int i = 0; i < NIN; i++) { x[i] = xv[i]; sx = fmaf(x[i], x[i], sx); }
        float y[NIN];
        #pragma unroll
        for (int j = 0; j < NIN; j++) y[j] = 0.0f;
        int tt = 0;
        #pragma unroll
        for (int i = 0; i < NIN; i++) {
            #pragma unroll
            for (int j = 0; j <= i; j++) {
                y[j] = fmaf(nn[tt], x[i], y[j]);
                tt++;
            }
        }
        float v = 0.0f;
        #pragma unroll
        for (int j = 0; j < NIN; j++) v = fmaf(y[j], y[j], v);
        out[row0 + tid] = v + 1e-6f * sx;
    }
}

extern "C" void kernel_launch(void* const* d_in, const int* in_sizes, int n_in,
                              void* d_out, int out_size)
{
    const float* pts = (const float*)d_in[0];
    const float* W0  = (const float*)d_in[1];
    const float* b0  = (const float*)d_in[2];
    const float* W1  = (const float*)d_in[3];
    const float* b1  = (const float*)d_in[4];
    const float* W2  = (const float*)d_in[5];
    const float* b2  = (const float*)d_in[6];
    float* out = (float*)d_out;

    const int B = in_sizes[0] / NIN;

    cudaFuncSetAttribute(ptpd_mma_kernel,
                         cudaFuncAttributeMaxDynamicSharedMemorySize, SMEM_BYTES);

    const int prep_threads = 64*32 + 32*64*32 + 32*20*32;
    prep_weights<<<(prep_threads + 255)/256, 256>>>(W0, W1, W2);

    ptpd_mma_kernel<<<B/TM, TH, SMEM_BYTES>>>(pts, b0, b1, b2, out);
}

// round 12
// speedup vs baseline: 4.1076x; 1.1149x over previous
#include <cuda_runtime.h>
#include <cuda_bf16.h>
#include <stdint.h>

#define TH 256
#define TM 32
#define HID 512
#define NIN 16
#define NOUT 136
#define HS 520              // H row stride (bf16): conflict-free for ldmatrix
#define XSTR 24             // X hi/lo row stride (bf16): 48B rows, conflict-free
#define NETS 137

#define XS_OFF  0                        // 32*16*4 = 2048
#define XH_OFF  2048                     // 32*24*2 = 1536
#define XL_OFF  (XH_OFF + 1536)
#define HH_OFF  (XL_OFF + 1536)          // 5120
#define HL_OFF  (HH_OFF + 33280)
#define SMEM_BYTES (HL_OFF + 33280)      // 71680
#define NET_OFF HH_OFF                   // netS overlays Hh (free after L2 MMAs)

// fragment-ordered weights: [ks][ng][lane] -> {bhi0, bhi1, blo0, blo1}
__device__ __align__(16) uint4 g_W0f[64 * 32];        // 32 KB (single k-step)
__device__ __align__(16) uint4 g_W1f[32 * 64 * 32];   // 1 MB
__device__ __align__(16) uint4 g_W2f[32 * 20 * 32];   // 320 KB (N padded to 160)

__device__ __forceinline__ uint32_t pack_bf2(float a, float b)
{
    __nv_bfloat162 p = __floats2bfloat162_rn(a, b);
    return *(uint32_t*)&p;
}

__device__ __forceinline__ uint4 make_frag(float v00, float v01, float v10, float v11)
{
    float h00 = __bfloat162float(__float2bfloat16(v00));
    float h01 = __bfloat162float(__float2bfloat16(v01));
    float h10 = __bfloat162float(__float2bfloat16(v10));
    float h11 = __bfloat162float(__float2bfloat16(v11));
    uint4 o;
    o.x = pack_bf2(h00, h01);
    o.y = pack_bf2(h10, h11);
    o.z = pack_bf2(v00 - h00, v01 - h01);
    o.w = pack_bf2(v10 - h10, v11 - h11);
    return o;
}

__global__ void prep_weights(const float* __restrict__ W0,
                             const float* __restrict__ W1,
                             const float* __restrict__ W2)
{
    int idx = blockIdx.x * blockDim.x + threadIdx.x;
    const int T0 = 64 * 32;
    const int T1 = 32 * 64 * 32;
    const int T2 = 32 * 20 * 32;
    if (idx < T0) {
        int lane = idx & 31, ng = idx >> 5;
        int g = lane >> 2, t = lane & 3;
        int n = ng * 8 + g;
        int k0 = 2 * t;
        g_W0f[idx] = make_frag(W0[(k0    )*HID + n], W0[(k0 + 1)*HID + n],
                               W0[(k0 + 8)*HID + n], W0[(k0 + 9)*HID + n]);
    } else if (idx < T0 + T1) {
        int i = idx - T0;
        int lane = i & 31, ng = (i >> 5) & 63, ks = i >> 11;
        int g = lane >> 2, t = lane & 3;
        int n = ng * 8 + g;
        int k0 = ks * 16 + 2 * t;
        g_W1f[i] = make_frag(W1[(k0    )*HID + n], W1[(k0 + 1)*HID + n],
                             W1[(k0 + 8)*HID + n], W1[(k0 + 9)*HID + n]);
    } else if (idx < T0 + T1 + T2) {
        int j = idx - T0 - T1;
        int lane = j & 31, ng = (j >> 5) % 20, ks = j / (20 * 32);
        int g = lane >> 2, t = lane & 3;
        int n = ng * 8 + g;
        int k0 = ks * 16 + 2 * t;
        float v00 = (n < NOUT) ? W2[(k0    )*NOUT + n] : 0.0f;
        float v01 = (n < NOUT) ? W2[(k0 + 1)*NOUT + n] : 0.0f;
        float v10 = (n < NOUT) ? W2[(k0 + 8)*NOUT + n] : 0.0f;
        float v11 = (n < NOUT) ? W2[(k0 + 9)*NOUT + n] : 0.0f;
        g_W2f[j] = make_frag(v00, v01, v10, v11);
    }
}

__device__ __forceinline__ void mma16816(float* d, const uint32_t* a,
                                         uint32_t b0, uint32_t b1)
{
    asm volatile(
        "mma.sync.aligned.m16n8k16.row.col.f32.bf16.bf16.f32 "
        "{%0,%1,%2,%3}, {%4,%5,%6,%7}, {%8,%9}, {%0,%1,%2,%3};\n"
        : "+f"(d[0]), "+f"(d[1]), "+f"(d[2]), "+f"(d[3])
        : "r"(a[0]), "r"(a[1]), "r"(a[2]), "r"(a[3]),
          "r"(b0), "r"(b1));
}

__device__ __forceinline__ void ldsm4(uint32_t* r, uint32_t saddr)
{
    asm volatile("ldmatrix.sync.aligned.m8n8.x4.shared.b16 {%0,%1,%2,%3}, [%4];\n"
                 : "=r"(r[0]), "=r"(r[1]), "=r"(r[2]), "=r"(r[3])
                 : "r"(saddr));
}

__device__ __forceinline__ float ftanh(float x)
{
    float xc = fminf(fmaxf(x, -15.0f), 15.0f);
    float e  = __expf(2.0f * xc);
    return __fdividef(e - 1.0f, e + 1.0f);
}

__device__ __forceinline__ void split_store2(__nv_bfloat16* Hh, __nv_bfloat16* Hl,
                                             int idx, float v0, float v1)
{
    __nv_bfloat162 hp = __floats2bfloat162_rn(v0, v1);
    float r0 = v0 - __bfloat162float(hp.x);
    float r1 = v1 - __bfloat162float(hp.y);
    __nv_bfloat162 lp = __floats2bfloat162_rn(r0, r1);
    *(__nv_bfloat162*)(Hh + idx) = hp;
    *(__nv_bfloat162*)(Hl + idx) = lp;
}

__global__ __launch_bounds__(TH, 2)
void ptpd_mma_kernel(const float* __restrict__ pts,
                     const float* __restrict__ b0,
                     const float* __restrict__ b1, const float* __restrict__ b2,
                     float* __restrict__ out)
{
    extern __shared__ char sm[];
    float*          Xs  = (float*)(sm + XS_OFF);
    __nv_bfloat16*  Xh  = (__nv_bfloat16*)(sm + XH_OFF);
    __nv_bfloat16*  Xl  = (__nv_bfloat16*)(sm + XL_OFF);
    __nv_bfloat16*  Hh  = (__nv_bfloat16*)(sm + HH_OFF);
    __nv_bfloat16*  Hl  = (__nv_bfloat16*)(sm + HL_OFF);
    float*          netS = (float*)(sm + NET_OFF);   // overlays Hh after L2 MMAs

    const uint32_t smb = (uint32_t)__cvta_generic_to_shared(sm);
    const uint32_t xhS = smb + XH_OFF;
    const uint32_t xlS = smb + XL_OFF;
    const uint32_t hhS = smb + HH_OFF;
    const uint32_t hlS = smb + HL_OFF;

    const int tid  = threadIdx.x;
    const int lane = tid & 31;
    const int wid  = tid >> 5;
    const int g    = lane >> 2;
    const int t    = lane & 3;
    const long row0 = (long)blockIdx.x * TM;

    const int arow  = lane & 15;
    const int acol8 = (lane >> 4) << 3;

    // ---------------- X tile: fp32 + hi/lo split ----------------
    for (int i = tid; i < TM*NIN; i += TH) {
        float x = pts[row0*NIN + i];
        Xs[i] = x;
        int r = i >> 4, c = i & 15;
        __nv_bfloat16 xh = __float2bfloat16(x);
        Xh[r*XSTR + c] = xh;
        Xl[r*XSTR + c] = __float2bfloat16(x - __bfloat162float(xh));
    }
    __syncthreads();

    // ---------------- layer 0 via MMA (K=16, 1 k-step) ----------------
    {
        float acc0[2][8][4];
        #pragma unroll
        for (int nt = 0; nt < 8; nt++) {
            int col = wid*64 + nt*8 + 2*t;
            float bv0 = b0[col], bv1 = b0[col + 1];
            #pragma unroll
            for (int mt = 0; mt < 2; mt++) {
                acc0[mt][nt][0] = bv0; acc0[mt][nt][1] = bv1;
                acc0[mt][nt][2] = bv0; acc0[mt][nt][3] = bv1;
            }
        }
        uint32_t xhf[2][4], xlf[2][4];
        #pragma unroll
        for (int mt = 0; mt < 2; mt++) {
            int ro = (mt*16 + arow)*XSTR + acol8;
            ldsm4(xhf[mt], xhS + ro*2);
            ldsm4(xlf[mt], xlS + ro*2);
        }
        const uint4* __restrict__ wp0 = g_W0f + (wid*8)*32 + lane;
        #pragma unroll
        for (int h = 0; h < 2; h++) {
            uint4 bv[4];
            #pragma unroll
            for (int j = 0; j < 4; j++)
                bv[j] = wp0[(h*4 + j)*32];
            #pragma unroll
            for (int j = 0; j < 4; j++)
                #pragma unroll
                for (int mt = 0; mt < 2; mt++) {
                    mma16816(acc0[mt][h*4 + j], xhf[mt], bv[j].x, bv[j].y);
                    mma16816(acc0[mt][h*4 + j], xhf[mt], bv[j].z, bv[j].w);
                    mma16816(acc0[mt][h*4 + j], xlf[mt], bv[j].x, bv[j].y);
                }
        }
        // tanh + split -> H0
        #pragma unroll
        for (int mt = 0; mt < 2; mt++)
            #pragma unroll
            for (int nt = 0; nt < 8; nt++) {
                int r   = mt*16 + g;
                int col = wid*64 + nt*8 + 2*t;
                split_store2(Hh, Hl, r*HS + col,
                             ftanh(acc0[mt][nt][0]), ftanh(acc0[mt][nt][1]));
                split_store2(Hh, Hl, (r + 8)*HS + col,
                             ftanh(acc0[mt][nt][2]), ftanh(acc0[mt][nt][3]));
            }
    }
    __syncthreads();

    // =============== layer 1: each warp owns 64 n-cols, 32 rows ===============
    {
        float acc1[2][8][4];
        #pragma unroll
        for (int nt = 0; nt < 8; nt++) {
            int col = wid*64 + nt*8 + 2*t;
            float bv0 = b1[col], bv1 = b1[col + 1];
            #pragma unroll
            for (int mt = 0; mt < 2; mt++) {
                acc1[mt][nt][0] = bv0; acc1[mt][nt][1] = bv1;
                acc1[mt][nt][2] = bv0; acc1[mt][nt][3] = bv1;
            }
        }

        // strength-reduced pointers: one IADD each per ks
        const uint4* __restrict__ wp = g_W1f + (wid*8)*32 + lane;
        uint32_t a0 = hhS + (uint32_t)(arow*HS + acol8)*2;
        uint32_t a1 = a0 + 16*HS*2;
        uint32_t l0 = hlS + (uint32_t)(arow*HS + acol8)*2;
        uint32_t l1 = l0 + 16*HS*2;

        for (int ks = 0; ks < 32; ks++) {
            uint4 bv[8];
            #pragma unroll
            for (int nt = 0; nt < 8; nt++)
                bv[nt] = wp[nt*32];
            wp += 64*32;

            uint32_t ah[2][4], al[2][4];
            ldsm4(ah[0], a0);
            ldsm4(al[0], l0);
            ldsm4(ah[1], a1);
            ldsm4(al[1], l1);
            a0 += 32; a1 += 32; l0 += 32; l1 += 32;

            #pragma unroll
            for (int nt = 0; nt < 8; nt++)
                #pragma unroll
                for (int mt = 0; mt < 2; mt++) {
                    mma16816(acc1[mt][nt], ah[mt], bv[nt].x, bv[nt].y);
                    mma16816(acc1[mt][nt], ah[mt], bv[nt].z, bv[nt].w);
                    mma16816(acc1[mt][nt], al[mt], bv[nt].x, bv[nt].y);
                }
        }

        __syncthreads();    // all warps done READING H0 before overwrite

        // tanh + split -> H1 (overwrites H0 buffers)
        #pragma unroll
        for (int mt = 0; mt < 2; mt++)
            #pragma unroll
            for (int nt = 0; nt < 8; nt++) {
                int r   = mt*16 + g;
                int col = wid*64 + nt*8 + 2*t;
                split_store2(Hh, Hl, r*HS + col,
                             ftanh(acc1[mt][nt][0]), ftanh(acc1[mt][nt][1]));
                split_store2(Hh, Hl, (r + 8)*HS + col,
                             ftanh(acc1[mt][nt][2]), ftanh(acc1[mt][nt][3]));
            }
    }
    __syncthreads();

    // =============== layer 2: 2 m-warps x 4 n-warps (N padded 160) ===============
    {
        const int wm = wid & 1;      // 16 rows each
        const int wn = wid >> 1;     // 40 cols (5 n-tiles)
        float acc2[5][4];
        #pragma unroll
        for (int nt = 0; nt < 5; nt++) {
            int col = wn*40 + nt*8 + 2*t;
            float bv0 = (col     < NOUT) ? b2[col]     : 0.0f;
            float bv1 = (col + 1 < NOUT) ? b2[col + 1] : 0.0f;
            acc2[nt][0] = bv0; acc2[nt][1] = bv1;
            acc2[nt][2] = bv0; acc2[nt][3] = bv1;
        }

        const uint4* __restrict__ wp2 = g_W2f + (wn*5)*32 + lane;
        uint32_t a0 = hhS + (uint32_t)((wm*16 + arow)*HS + acol8)*2;
        uint32_t l0 = hlS + (uint32_t)((wm*16 + arow)*HS + acol8)*2;

        for (int ks = 0; ks < 32; ks++) {
            uint4 bv[5];
            #pragma unroll
            for (int nt = 0; nt < 5; nt++)
                bv[nt] = wp2[nt*32];
            wp2 += 20*32;

            uint32_t ah[4], al[4];
            ldsm4(ah, a0);
            ldsm4(al, l0);
            a0 += 32; l0 += 32;

            #pragma unroll
            for (int nt = 0; nt < 5; nt++) {
                mma16816(acc2[nt], ah, bv[nt].x, bv[nt].y);
                mma16816(acc2[nt], ah, bv[nt].z, bv[nt].w);
                mma16816(acc2[nt], al, bv[nt].x, bv[nt].y);
            }
        }

        __syncthreads();   // all warps done READING H1 -> netS overlay safe

        // net -> smem (overlays Hh)
        #pragma unroll
        for (int nt = 0; nt < 5; nt++) {
            int r   = wm*16 + g;
            int col = wn*40 + nt*8 + 2*t;
            if (col + 1 < NOUT) {
                netS[r*NETS + col]           = acc2[nt][0];
                netS[r*NETS + col + 1]       = acc2[nt][1];
                netS[(r + 8)*NETS + col]     = acc2[nt][2];
                netS[(r + 8)*NETS + col + 1] = acc2[nt][3];
            }
        }
    }
    __syncthreads();

    // ---------------- quadratic form ----------------
    if (tid < TM) {
        const float* nn = netS + tid*NETS;
        const float* xv = Xs + tid*NIN;
        float x[NIN], sx = 0.0f;
        #pragma unroll
        for (int i = 0; i < NIN; i++) { x[i] = xv[i]; sx = fmaf(x[i], x[i], sx); }
        float y[NIN];
        #pragma unroll
        for (int j = 0; j < NIN; j++) y[j] = 0.0f;
        int tt = 0;
        #pragma unroll
        for (int i = 0; i < NIN; i++) {
            #pragma unroll
            for (int j = 0; j <= i; j++) {
                y[j] = fmaf(nn[tt], x[i], y[j]);
                tt++;
            }
        }
        float v = 0.0f;
        #pragma unroll
        for (int j = 0; j < NIN; j++) v = fmaf(y[j], y[j], v);
        out[row0 + tid] = v + 1e-6f * sx;
    }
}

extern "C" void kernel_launch(void* const* d_in, const int* in_sizes, int n_in,
                              void* d_out, int out_size)
{
    const float* pts = (const float*)d_in[0];
    const float* W0  = (const float*)d_in[1];
    const float* b0  = (const float*)d_in[2];
    const float* W1  = (const float*)d_in[3];
    const float* b1  = (const float*)d_in[4];
    const float* W2  = (const float*)d_in[5];
    const float* b2  = (const float*)d_in[6];
    float* out = (float*)d_out;

    const int B = in_sizes[0] / NIN;

    cudaFuncSetAttribute(ptpd_mma_kernel,
                         cudaFuncAttributeMaxDynamicSharedMemorySize, SMEM_BYTES);

    const int prep_threads = 64*32 + 32*64*32 + 32*20*32;
    prep_weights<<<(prep_threads + 255)/256, 256>>>(W0, W1, W2);

    ptpd_mma_kernel<<<B/TM, TH, SMEM_BYTES>>>(pts, b0, b1, b2, out);
}

// round 13
// speedup vs baseline: 5.1501x; 1.2538x over previous
#include <cuda_runtime.h>
#include <cuda_fp16.h>
#include <stdint.h>

#define TH 256
#define TM 32
#define HID 512
#define NIN 16
#define NOUT 136
#define HS 520              // H row stride (fp16): conflict-free for ldmatrix
#define XSTR 24             // X hi/lo row stride (fp16)
#define NETS 137

#define XS_OFF  0                        // 32*16*4 = 2048
#define XH_OFF  2048                     // 32*24*2 = 1536
#define XL_OFF  (XH_OFF + 1536)
#define HH_OFF  (XL_OFF + 1536)          // 5120
#define HL_OFF  (HH_OFF + 33280)
#define SMEM_BYTES (HL_OFF + 33280)      // 71680
#define NET_OFF HH_OFF                   // netS overlays Hh (free after L2 MMAs)

// fragment-ordered fp16 weights
__device__ __align__(16) uint4 g_W0f[64 * 32];        // hi/lo   32 KB
__device__ __align__(16) uint2 g_W1f[32 * 64 * 32];   // hi only 512 KB
__device__ __align__(16) uint4 g_W2f[32 * 20 * 32];   // hi/lo   320 KB

__device__ __forceinline__ uint32_t pack_h2(float a, float b)
{
    __half2 p = __floats2half2_rn(a, b);
    return *(uint32_t*)&p;
}

// fp16 hi/lo fragment (for W0, W2)
__device__ __forceinline__ uint4 make_frag_h(float v00, float v01, float v10, float v11)
{
    float h00 = __half2float(__float2half_rn(v00));
    float h01 = __half2float(__float2half_rn(v01));
    float h10 = __half2float(__float2half_rn(v10));
    float h11 = __half2float(__float2half_rn(v11));
    uint4 o;
    o.x = pack_h2(h00, h01);
    o.y = pack_h2(h10, h11);
    o.z = pack_h2(v00 - h00, v01 - h01);
    o.w = pack_h2(v10 - h10, v11 - h11);
    return o;
}

__global__ void prep_weights(const float* __restrict__ W0,
                             const float* __restrict__ W1,
                             const float* __restrict__ W2)
{
    int idx = blockIdx.x * blockDim.x + threadIdx.x;
    const int T0 = 64 * 32;
    const int T1 = 32 * 64 * 32;
    const int T2 = 32 * 20 * 32;
    if (idx < T0) {
        int lane = idx & 31, ng = idx >> 5;
        int g = lane >> 2, t = lane & 3;
        int n = ng * 8 + g;
        int k0 = 2 * t;
        g_W0f[idx] = make_frag_h(W0[(k0    )*HID + n], W0[(k0 + 1)*HID + n],
                                 W0[(k0 + 8)*HID + n], W0[(k0 + 9)*HID + n]);
    } else if (idx < T0 + T1) {
        int i = idx - T0;
        int lane = i & 31, ng = (i >> 5) & 63, ks = i >> 11;
        int g = lane >> 2, t = lane & 3;
        int n = ng * 8 + g;
        int k0 = ks * 16 + 2 * t;
        uint2 o;
        o.x = pack_h2(W1[(k0    )*HID + n], W1[(k0 + 1)*HID + n]);
        o.y = pack_h2(W1[(k0 + 8)*HID + n], W1[(k0 + 9)*HID + n]);
        g_W1f[i] = o;
    } else if (idx < T0 + T1 + T2) {
        int j = idx - T0 - T1;
        int lane = j & 31, ng = (j >> 5) % 20, ks = j / (20 * 32);
        int g = lane >> 2, t = lane & 3;
        int n = ng * 8 + g;
        int k0 = ks * 16 + 2 * t;
        float v00 = (n < NOUT) ? W2[(k0    )*NOUT + n] : 0.0f;
        float v01 = (n < NOUT) ? W2[(k0 + 1)*NOUT + n] : 0.0f;
        float v10 = (n < NOUT) ? W2[(k0 + 8)*NOUT + n] : 0.0f;
        float v11 = (n < NOUT) ? W2[(k0 + 9)*NOUT + n] : 0.0f;
        g_W2f[j] = make_frag_h(v00, v01, v10, v11);
    }
}

__device__ __forceinline__ void mma16816h(float* d, const uint32_t* a,
                                          uint32_t b0, uint32_t b1)
{
    asm volatile(
        "mma.sync.aligned.m16n8k16.row.col.f32.f16.f16.f32 "
        "{%0,%1,%2,%3}, {%4,%5,%6,%7}, {%8,%9}, {%0,%1,%2,%3};\n"
        : "+f"(d[0]), "+f"(d[1]), "+f"(d[2]), "+f"(d[3])
        : "r"(a[0]), "r"(a[1]), "r"(a[2]), "r"(a[3]),
          "r"(b0), "r"(b1));
}

__device__ __forceinline__ void ldsm4(uint32_t* r, uint32_t saddr)
{
    asm volatile("ldmatrix.sync.aligned.m8n8.x4.shared.b16 {%0,%1,%2,%3}, [%4];\n"
                 : "=r"(r[0]), "=r"(r[1]), "=r"(r[2]), "=r"(r[3])
                 : "r"(saddr));
}

__device__ __forceinline__ float ftanh(float x)
{
    float xc = fminf(fmaxf(x, -15.0f), 15.0f);
    float e  = __expf(2.0f * xc);
    return __fdividef(e - 1.0f, e + 1.0f);
}

__device__ __forceinline__ void split_store2(__half* Hh, __half* Hl,
                                             int idx, float v0, float v1)
{
    __half2 hp = __floats2half2_rn(v0, v1);
    float r0 = v0 - __low2float(hp);
    float r1 = v1 - __high2float(hp);
    __half2 lp = __floats2half2_rn(r0, r1);
    *(__half2*)(Hh + idx) = hp;
    *(__half2*)(Hl + idx) = lp;
}

__global__ __launch_bounds__(TH, 2)
void ptpd_mma_kernel(const float* __restrict__ pts,
                     const float* __restrict__ b0,
                     const float* __restrict__ b1, const float* __restrict__ b2,
                     float* __restrict__ out)
{
    extern __shared__ char sm[];
    float*  Xs  = (float*)(sm + XS_OFF);
    __half* Xh  = (__half*)(sm + XH_OFF);
    __half* Xl  = (__half*)(sm + XL_OFF);
    __half* Hh  = (__half*)(sm + HH_OFF);
    __half* Hl  = (__half*)(sm + HL_OFF);
    float*  netS = (float*)(sm + NET_OFF);   // overlays Hh after L2 MMAs

    const uint32_t smb = (uint32_t)__cvta_generic_to_shared(sm);
    const uint32_t xhS = smb + XH_OFF;
    const uint32_t xlS = smb + XL_OFF;
    const uint32_t hhS = smb + HH_OFF;
    const uint32_t hlS = smb + HL_OFF;

    const int tid  = threadIdx.x;
    const int lane = tid & 31;
    const int wid  = tid >> 5;
    const int g    = lane >> 2;
    const int t    = lane & 3;
    const long row0 = (long)blockIdx.x * TM;

    const int arow  = lane & 15;
    const int acol8 = (lane >> 4) << 3;

    // ---------------- X tile: fp32 + hi/lo split ----------------
    for (int i = tid; i < TM*NIN; i += TH) {
        float x = pts[row0*NIN + i];
        Xs[i] = x;
        int r = i >> 4, c = i & 15;
        __half xh = __float2half_rn(x);
        Xh[r*XSTR + c] = xh;
        Xl[r*XSTR + c] = __float2half_rn(x - __half2float(xh));
    }
    __syncthreads();

    // ---------------- layer 0 via MMA (K=16, 3-term fp16) ----------------
    {
        float acc0[2][8][4];
        #pragma unroll
        for (int nt = 0; nt < 8; nt++) {
            int col = wid*64 + nt*8 + 2*t;
            float bv0 = b0[col], bv1 = b0[col + 1];
            #pragma unroll
            for (int mt = 0; mt < 2; mt++) {
                acc0[mt][nt][0] = bv0; acc0[mt][nt][1] = bv1;
                acc0[mt][nt][2] = bv0; acc0[mt][nt][3] = bv1;
            }
        }
        uint32_t xhf[2][4], xlf[2][4];
        #pragma unroll
        for (int mt = 0; mt < 2; mt++) {
            int ro = (mt*16 + arow)*XSTR + acol8;
            ldsm4(xhf[mt], xhS + ro*2);
            ldsm4(xlf[mt], xlS + ro*2);
        }
        const uint4* __restrict__ wp0 = g_W0f + (wid*8)*32 + lane;
        #pragma unroll
        for (int h = 0; h < 2; h++) {
            uint4 bv[4];
            #pragma unroll
            for (int j = 0; j < 4; j++)
                bv[j] = wp0[(h*4 + j)*32];
            #pragma unroll
            for (int j = 0; j < 4; j++)
                #pragma unroll
                for (int mt = 0; mt < 2; mt++) {
                    mma16816h(acc0[mt][h*4 + j], xhf[mt], bv[j].x, bv[j].y);
                    mma16816h(acc0[mt][h*4 + j], xhf[mt], bv[j].z, bv[j].w);
                    mma16816h(acc0[mt][h*4 + j], xlf[mt], bv[j].x, bv[j].y);
                }
        }
        // tanh + split -> H0
        #pragma unroll
        for (int mt = 0; mt < 2; mt++)
            #pragma unroll
            for (int nt = 0; nt < 8; nt++) {
                int r   = mt*16 + g;
                int col = wid*64 + nt*8 + 2*t;
                split_store2(Hh, Hl, r*HS + col,
                             ftanh(acc0[mt][nt][0]), ftanh(acc0[mt][nt][1]));
                split_store2(Hh, Hl, (r + 8)*HS + col,
                             ftanh(acc0[mt][nt][2]), ftanh(acc0[mt][nt][3]));
            }
    }
    __syncthreads();

    // ====== layer 1: 2-term fp16 (A split, W single) — each warp 64 n-cols ======
    {
        float acc1[2][8][4];
        #pragma unroll
        for (int nt = 0; nt < 8; nt++) {
            int col = wid*64 + nt*8 + 2*t;
            float bv0 = b1[col], bv1 = b1[col + 1];
            #pragma unroll
            for (int mt = 0; mt < 2; mt++) {
                acc1[mt][nt][0] = bv0; acc1[mt][nt][1] = bv1;
                acc1[mt][nt][2] = bv0; acc1[mt][nt][3] = bv1;
            }
        }

        const uint2* __restrict__ wp = g_W1f + (wid*8)*32 + lane;
        uint32_t a0 = hhS + (uint32_t)(arow*HS + acol8)*2;
        uint32_t a1 = a0 + 16*HS*2;
        uint32_t l0 = hlS + (uint32_t)(arow*HS + acol8)*2;
        uint32_t l1 = l0 + 16*HS*2;

        for (int ks = 0; ks < 32; ks++) {
            uint2 bv[8];
            #pragma unroll
            for (int nt = 0; nt < 8; nt++)
                bv[nt] = wp[nt*32];
            wp += 64*32;

            uint32_t ah[2][4], al[2][4];
            ldsm4(ah[0], a0);
            ldsm4(al[0], l0);
            ldsm4(ah[1], a1);
            ldsm4(al[1], l1);
            a0 += 32; a1 += 32; l0 += 32; l1 += 32;

            #pragma unroll
            for (int nt = 0; nt < 8; nt++)
                #pragma unroll
                for (int mt = 0; mt < 2; mt++) {
                    mma16816h(acc1[mt][nt], ah[mt], bv[nt].x, bv[nt].y);
                    mma16816h(acc1[mt][nt], al[mt], bv[nt].x, bv[nt].y);
                }
        }

        __syncthreads();    // all warps done READING H0 before overwrite

        // tanh + split -> H1 (overwrites H0 buffers)
        #pragma unroll
        for (int mt = 0; mt < 2; mt++)
            #pragma unroll
            for (int nt = 0; nt < 8; nt++) {
                int r   = mt*16 + g;
                int col = wid*64 + nt*8 + 2*t;
                split_store2(Hh, Hl, r*HS + col,
                             ftanh(acc1[mt][nt][0]), ftanh(acc1[mt][nt][1]));
                split_store2(Hh, Hl, (r + 8)*HS + col,
                             ftanh(acc1[mt][nt][2]), ftanh(acc1[mt][nt][3]));
            }
    }
    __syncthreads();

    // ====== layer 2: 3-term fp16, 2 m-warps x 4 n-warps (N padded 160) ======
    {
        const int wm = wid & 1;      // 16 rows each
        const int wn = wid >> 1;     // 40 cols (5 n-tiles)
        float acc2[5][4];
        #pragma unroll
        for (int nt = 0; nt < 5; nt++) {
            int col = wn*40 + nt*8 + 2*t;
            float bv0 = (col     < NOUT) ? b2[col]     : 0.0f;
            float bv1 = (col + 1 < NOUT) ? b2[col + 1] : 0.0f;
            acc2[nt][0] = bv0; acc2[nt][1] = bv1;
            acc2[nt][2] = bv0; acc2[nt][3] = bv1;
        }

        const uint4* __restrict__ wp2 = g_W2f + (wn*5)*32 + lane;
        uint32_t a0 = hhS + (uint32_t)((wm*16 + arow)*HS + acol8)*2;
        uint32_t l0 = hlS + (uint32_t)((wm*16 + arow)*HS + acol8)*2;

        for (int ks = 0; ks < 32; ks++) {
            uint4 bv[5];
            #pragma unroll
            for (int nt = 0; nt < 5; nt++)
                bv[nt] = wp2[nt*32];
            wp2 += 20*32;

            uint32_t ah[4], al[4];
            ldsm4(ah, a0);
            ldsm4(al, l0);
            a0 += 32; l0 += 32;

            #pragma unroll
            for (int nt = 0; nt < 5; nt++) {
                mma16816h(acc2[nt], ah, bv[nt].x, bv[nt].y);
                mma16816h(acc2[nt], ah, bv[nt].z, bv[nt].w);
                mma16816h(acc2[nt], al, bv[nt].x, bv[nt].y);
            }
        }

        __syncthreads();   // all warps done READING H1 -> netS overlay safe

        // net -> smem (overlays Hh)
        #pragma unroll
        for (int nt = 0; nt < 5; nt++) {
            int r   = wm*16 + g;
            int col = wn*40 + nt*8 + 2*t;
            if (col + 1 < NOUT) {
                netS[r*NETS + col]           = acc2[nt][0];
                netS[r*NETS + col + 1]       = acc2[nt][1];
                netS[(r + 8)*NETS + col]     = acc2[nt][2];
                netS[(r + 8)*NETS + col + 1] = acc2[nt][3];
            }
        }
    }
    __syncthreads();

    // ---------------- quadratic form ----------------
    if (tid < TM) {
        const float* nn = netS + tid*NETS;
        const float* xv = Xs + tid*NIN;
        float x[NIN], sx = 0.0f;
        #pragma unroll
        for (int i = 0; i < NIN; i++) { x[i] = xv[i]; sx = fmaf(x[i], x[i], sx); }
        float y[NIN];
        #pragma unroll
        for (int j = 0; j < NIN; j++) y[j] = 0.0f;
        int tt = 0;
        #pragma unroll
        for (int i = 0; i < NIN; i++) {
            #pragma unroll
            for (int j = 0; j <= i; j++) {
                y[j] = fmaf(nn[tt], x[i], y[j]);
                tt++;
            }
        }
        float v = 0.0f;
        #pragma unroll
        for (int j = 0; j < NIN; j++) v = fmaf(y[j], y[j], v);
        out[row0 + tid] = v + 1e-6f * sx;
    }
}

extern "C" void kernel_launch(void* const* d_in, const int* in_sizes, int n_in,
                              void* d_out, int out_size)
{
    const float* pts = (const float*)d_in[0];
    const float* W0  = (const float*)d_in[1];
    const float* b0  = (const float*)d_in[2];
    const float* W1  = (const float*)d_in[3];
    const float* b1  = (const float*)d_in[4];
    const float* W2  = (const float*)d_in[5];
    const float* b2  = (const float*)d_in[6];
    float* out = (float*)d_out;

    const int B = in_sizes[0] / NIN;

    cudaFuncSetAttribute(ptpd_mma_kernel,
                         cudaFuncAttributeMaxDynamicSharedMemorySize, SMEM_BYTES);

    const int prep_threads = 64*32 + 32*64*32 + 32*20*32;
    prep_weights<<<(prep_threads + 255)/256, 256>>>(W0, W1, W2);

    ptpd_mma_kernel<<<B/TM, TH, SMEM_BYTES>>>(pts, b0, b1, b2, out);
}

// round 14
// speedup vs baseline: 8.6551x; 1.6806x over previous
#include <cuda_runtime.h>
#include <cuda_fp16.h>
#include <stdint.h>

#define TH 256
#define TM 32
#define HID 512
#define NIN 16
#define NOUT 136
#define HS 520              // H row stride (fp16): conflict-free for ldmatrix
#define XSTR 24             // X row stride (fp16)
#define NETS 137

#define XS_OFF  0                        // 32*16*4 = 2048
#define XH_OFF  2048                     // 32*24*2 = 1536
#define HH_OFF  (XH_OFF + 1536)          // 3584
#define SMEM_BYTES (HH_OFF + 33280)      // 36864
#define NET_OFF HH_OFF                   // netS overlays Hh (free after L2 MMAs)

// fragment-ordered single-fp16 weights: [ks][ng][lane] -> {b0, b1}
__device__ __align__(16) uint2 g_W0f[64 * 32];        // 16 KB
__device__ __align__(16) uint2 g_W1f[32 * 64 * 32];   // 512 KB
__device__ __align__(16) uint2 g_W2f[32 * 20 * 32];   // 160 KB (N padded to 160)

__device__ __forceinline__ uint32_t pack_h2(float a, float b)
{
    __half2 p = __floats2half2_rn(a, b);
    return *(uint32_t*)&p;
}

__global__ void prep_weights(const float* __restrict__ W0,
                             const float* __restrict__ W1,
                             const float* __restrict__ W2)
{
    int idx = blockIdx.x * blockDim.x + threadIdx.x;
    const int T0 = 64 * 32;
    const int T1 = 32 * 64 * 32;
    const int T2 = 32 * 20 * 32;
    if (idx < T0) {
        int lane = idx & 31, ng = idx >> 5;
        int g = lane >> 2, t = lane & 3;
        int n = ng * 8 + g;
        int k0 = 2 * t;
        uint2 o;
        o.x = pack_h2(W0[(k0    )*HID + n], W0[(k0 + 1)*HID + n]);
        o.y = pack_h2(W0[(k0 + 8)*HID + n], W0[(k0 + 9)*HID + n]);
        g_W0f[idx] = o;
    } else if (idx < T0 + T1) {
        int i = idx - T0;
        int lane = i & 31, ng = (i >> 5) & 63, ks = i >> 11;
        int g = lane >> 2, t = lane & 3;
        int n = ng * 8 + g;
        int k0 = ks * 16 + 2 * t;
        uint2 o;
        o.x = pack_h2(W1[(k0    )*HID + n], W1[(k0 + 1)*HID + n]);
        o.y = pack_h2(W1[(k0 + 8)*HID + n], W1[(k0 + 9)*HID + n]);
        g_W1f[i] = o;
    } else if (idx < T0 + T1 + T2) {
        int j = idx - T0 - T1;
        int lane = j & 31, ng = (j >> 5) % 20, ks = j / (20 * 32);
        int g = lane >> 2, t = lane & 3;
        int n = ng * 8 + g;
        int k0 = ks * 16 + 2 * t;
        float v00 = (n < NOUT) ? W2[(k0    )*NOUT + n] : 0.0f;
        float v01 = (n < NOUT) ? W2[(k0 + 1)*NOUT + n] : 0.0f;
        float v10 = (n < NOUT) ? W2[(k0 + 8)*NOUT + n] : 0.0f;
        float v11 = (n < NOUT) ? W2[(k0 + 9)*NOUT + n] : 0.0f;
        uint2 o;
        o.x = pack_h2(v00, v01);
        o.y = pack_h2(v10, v11);
        g_W2f[j] = o;
    }
}

__device__ __forceinline__ void mma16816h(float* d, const uint32_t* a,
                                          uint32_t b0, uint32_t b1)
{
    asm volatile(
        "mma.sync.aligned.m16n8k16.row.col.f32.f16.f16.f32 "
        "{%0,%1,%2,%3}, {%4,%5,%6,%7}, {%8,%9}, {%0,%1,%2,%3};\n"
        : "+f"(d[0]), "+f"(d[1]), "+f"(d[2]), "+f"(d[3])
        : "r"(a[0]), "r"(a[1]), "r"(a[2]), "r"(a[3]),
          "r"(b0), "r"(b1));
}

__device__ __forceinline__ void ldsm4(uint32_t* r, uint32_t saddr)
{
    asm volatile("ldmatrix.sync.aligned.m8n8.x4.shared.b16 {%0,%1,%2,%3}, [%4];\n"
                 : "=r"(r[0]), "=r"(r[1]), "=r"(r[2]), "=r"(r[3])
                 : "r"(saddr));
}

__device__ __forceinline__ float ftanh(float x)
{
    float xc = fminf(fmaxf(x, -15.0f), 15.0f);
    float e  = __expf(2.0f * xc);
    return __fdividef(e - 1.0f, e + 1.0f);
}

__global__ __launch_bounds__(TH, 2)
void ptpd_mma_kernel(const float* __restrict__ pts,
                     const float* __restrict__ b0,
                     const float* __restrict__ b1, const float* __restrict__ b2,
                     float* __restrict__ out)
{
    extern __shared__ char sm[];
    float*  Xs  = (float*)(sm + XS_OFF);
    __half* Xh  = (__half*)(sm + XH_OFF);
    __half* Hh  = (__half*)(sm + HH_OFF);
    float*  netS = (float*)(sm + NET_OFF);   // overlays Hh after L2 MMAs

    const uint32_t smb = (uint32_t)__cvta_generic_to_shared(sm);
    const uint32_t xhS = smb + XH_OFF;
    const uint32_t hhS = smb + HH_OFF;

    const int tid  = threadIdx.x;
    const int lane = tid & 31;
    const int wid  = tid >> 5;
    const int g    = lane >> 2;
    const int t    = lane & 3;
    const long row0 = (long)blockIdx.x * TM;

    const int arow  = lane & 15;
    const int acol8 = (lane >> 4) << 3;

    // ---------------- X tile: fp32 + fp16 copy ----------------
    for (int i = tid; i < TM*NIN; i += TH) {
        float x = pts[row0*NIN + i];
        Xs[i] = x;
        int r = i >> 4, c = i & 15;
        Xh[r*XSTR + c] = __float2half_rn(x);
    }
    __syncthreads();

    // ---------------- layer 0 via MMA (K=16, single-term fp16) ----------------
    {
        float acc0[2][8][4];
        #pragma unroll
        for (int nt = 0; nt < 8; nt++) {
            int col = wid*64 + nt*8 + 2*t;
            float bv0 = b0[col], bv1 = b0[col + 1];
            #pragma unroll
            for (int mt = 0; mt < 2; mt++) {
                acc0[mt][nt][0] = bv0; acc0[mt][nt][1] = bv1;
                acc0[mt][nt][2] = bv0; acc0[mt][nt][3] = bv1;
            }
        }
        uint32_t xhf[2][4];
        #pragma unroll
        for (int mt = 0; mt < 2; mt++) {
            int ro = (mt*16 + arow)*XSTR + acol8;
            ldsm4(xhf[mt], xhS + ro*2);
        }
        const uint2* __restrict__ wp0 = g_W0f + (wid*8)*32 + lane;
        uint2 bv[8];
        #pragma unroll
        for (int nt = 0; nt < 8; nt++)
            bv[nt] = wp0[nt*32];
        #pragma unroll
        for (int nt = 0; nt < 8; nt++)
            #pragma unroll
            for (int mt = 0; mt < 2; mt++)
                mma16816h(acc0[mt][nt], xhf[mt], bv[nt].x, bv[nt].y);

        // tanh -> H0 (fp16)
        #pragma unroll
        for (int mt = 0; mt < 2; mt++)
            #pragma unroll
            for (int nt = 0; nt < 8; nt++) {
                int r   = mt*16 + g;
                int col = wid*64 + nt*8 + 2*t;
                *(__half2*)(Hh + r*HS + col) =
                    __floats2half2_rn(ftanh(acc0[mt][nt][0]), ftanh(acc0[mt][nt][1]));
                *(__half2*)(Hh + (r + 8)*HS + col) =
                    __floats2half2_rn(ftanh(acc0[mt][nt][2]), ftanh(acc0[mt][nt][3]));
            }
    }
    __syncthreads();

    // ====== layer 1: single-term fp16 — each warp 64 n-cols, 32 rows ======
    {
        float acc1[2][8][4];
        #pragma unroll
        for (int nt = 0; nt < 8; nt++) {
            int col = wid*64 + nt*8 + 2*t;
            float bv0 = b1[col], bv1 = b1[col + 1];
            #pragma unroll
            for (int mt = 0; mt < 2; mt++) {
                acc1[mt][nt][0] = bv0; acc1[mt][nt][1] = bv1;
                acc1[mt][nt][2] = bv0; acc1[mt][nt][3] = bv1;
            }
        }

        const uint2* __restrict__ wp = g_W1f + (wid*8)*32 + lane;
        uint32_t a0 = hhS + (uint32_t)(arow*HS + acol8)*2;
        uint32_t a1 = a0 + 16*HS*2;

        for (int ks = 0; ks < 32; ks++) {
            uint2 bv[8];
            #pragma unroll
            for (int nt = 0; nt < 8; nt++)
                bv[nt] = wp[nt*32];
            wp += 64*32;

            uint32_t ah[2][4];
            ldsm4(ah[0], a0);
            ldsm4(ah[1], a1);
            a0 += 32; a1 += 32;

            #pragma unroll
            for (int nt = 0; nt < 8; nt++)
                #pragma unroll
                for (int mt = 0; mt < 2; mt++)
                    mma16816h(acc1[mt][nt], ah[mt], bv[nt].x, bv[nt].y);
        }

        __syncthreads();    // all warps done READING H0 before overwrite

        // tanh -> H1 (overwrites H0)
        #pragma unroll
        for (int mt = 0; mt < 2; mt++)
            #pragma unroll
            for (int nt = 0; nt < 8; nt++) {
                int r   = mt*16 + g;
                int col = wid*64 + nt*8 + 2*t;
                *(__half2*)(Hh + r*HS + col) =
                    __floats2half2_rn(ftanh(acc1[mt][nt][0]), ftanh(acc1[mt][nt][1]));
                *(__half2*)(Hh + (r + 8)*HS + col) =
                    __floats2half2_rn(ftanh(acc1[mt][nt][2]), ftanh(acc1[mt][nt][3]));
            }
    }
    __syncthreads();

    // ====== layer 2: single-term fp16, 2 m-warps x 4 n-warps (N padded 160) ======
    {
        const int wm = wid & 1;      // 16 rows each
        const int wn = wid >> 1;     // 40 cols (5 n-tiles)
        float acc2[5][4];
        #pragma unroll
        for (int nt = 0; nt < 5; nt++) {
            int col = wn*40 + nt*8 + 2*t;
            float bv0 = (col     < NOUT) ? b2[col]     : 0.0f;
            float bv1 = (col + 1 < NOUT) ? b2[col + 1] : 0.0f;
            acc2[nt][0] = bv0; acc2[nt][1] = bv1;
            acc2[nt][2] = bv0; acc2[nt][3] = bv1;
        }

        const uint2* __restrict__ wp2 = g_W2f + (wn*5)*32 + lane;
        uint32_t a0 = hhS + (uint32_t)((wm*16 + arow)*HS + acol8)*2;

        for (int ks = 0; ks < 32; ks++) {
            uint2 bv[5];
            #pragma unroll
            for (int nt = 0; nt < 5; nt++)
                bv[nt] = wp2[nt*32];
            wp2 += 20*32;

            uint32_t ah[4];
            ldsm4(ah, a0);
            a0 += 32;

            #pragma unroll
            for (int nt = 0; nt < 5; nt++)
                mma16816h(acc2[nt], ah, bv[nt].x, bv[nt].y);
        }

        __syncthreads();   // all warps done READING H1 -> netS overlay safe

        // net -> smem (overlays Hh)
        #pragma unroll
        for (int nt = 0; nt < 5; nt++) {
            int r   = wm*16 + g;
            int col = wn*40 + nt*8 + 2*t;
            if (col + 1 < NOUT) {
                netS[r*NETS + col]           = acc2[nt][0];
                netS[r*NETS + col + 1]       = acc2[nt][1];
                netS[(r + 8)*NETS + col]     = acc2[nt][2];
                netS[(r + 8)*NETS + col + 1] = acc2[nt][3];
            }
        }
    }
    __syncthreads();

    // ---------------- quadratic form ----------------
    if (tid < TM) {
        const float* nn = netS + tid*NETS;
        const float* xv = Xs + tid*NIN;
        float x[NIN], sx = 0.0f;
        #pragma unroll
        for (int i = 0; i < NIN; i++) { x[i] = xv[i]; sx = fmaf(x[i], x[i], sx); }
        float y[NIN];
        #pragma unroll
        for (int j = 0; j < NIN; j++) y[j] = 0.0f;
        int tt = 0;
        #pragma unroll
        for (int i = 0; i < NIN; i++) {
            #pragma unroll
            for (int j = 0; j <= i; j++) {
                y[j] = fmaf(nn[tt], x[i], y[j]);
                tt++;
            }
        }
        float v = 0.0f;
        #pragma unroll
        for (int j = 0; j < NIN; j++) v = fmaf(y[j], y[j], v);
        out[row0 + tid] = v + 1e-6f * sx;
    }
}

extern "C" void kernel_launch(void* const* d_in, const int* in_sizes, int n_in,
                              void* d_out, int out_size)
{
    const float* pts = (const float*)d_in[0];
    const float* W0  = (const float*)d_in[1];
    const float* b0  = (const float*)d_in[2];
    const float* W1  = (const float*)d_in[3];
    const float* b1  = (const float*)d_in[4];
    const float* W2  = (const float*)d_in[5];
    const float* b2  = (const float*)d_in[6];
    float* out = (float*)d_out;

    const int B = in_sizes[0] / NIN;

    cudaFuncSetAttribute(ptpd_mma_kernel,
                         cudaFuncAttributeMaxDynamicSharedMemorySize, SMEM_BYTES);

    const int prep_threads = 64*32 + 32*64*32 + 32*20*32;
    prep_weights<<<(prep_threads + 255)/256, 256>>>(W0, W1, W2);

    ptpd_mma_kernel<<<B/TM, TH, SMEM_BYTES>>>(pts, b0, b1, b2, out);
}

// round 15
// speedup vs baseline: 10.1643x; 1.1744x over previous
#include <cuda_runtime.h>
#include <cuda_fp16.h>
#include <stdint.h>

#define TH 256
#define TM 32
#define HID 512
#define NIN 16
#define NOUT 136
#define HS 520              // H row stride (fp16): conflict-free for ldmatrix
#define XSTR 24             // X row stride (fp16)
#define NETS 137

#define XS_OFF  0                        // 32*16*4 = 2048
#define XH_OFF  2048                     // 32*24*2 = 1536
#define HH_OFF  (XH_OFF + 1536)          // 3584
#define SMEM_BYTES (HH_OFF + 33280)      // 36864
#define NET_OFF HH_OFF                   // netS overlays Hh (free after L2 MMAs)

// fragment-ordered single-fp16 weights: [ks][ng][lane] -> {b0, b1}
// +1 k-step of padding: the rotating prefetch reads (but never uses) ks==32.
__device__ __align__(16) uint2 g_W0f[64 * 32];          // 16 KB
__device__ __align__(16) uint2 g_W1f[33 * 64 * 32];     // 528 KB
__device__ __align__(16) uint2 g_W2f[33 * 20 * 32];     // 165 KB (N padded to 160)

__device__ __forceinline__ uint32_t pack_h2(float a, float b)
{
    __half2 p = __floats2half2_rn(a, b);
    return *(uint32_t*)&p;
}

__global__ void prep_weights(const float* __restrict__ W0,
                             const float* __restrict__ W1,
                             const float* __restrict__ W2)
{
    int idx = blockIdx.x * blockDim.x + threadIdx.x;
    const int T0 = 64 * 32;
    const int T1 = 32 * 64 * 32;
    const int T2 = 32 * 20 * 32;
    if (idx < T0) {
        int lane = idx & 31, ng = idx >> 5;
        int g = lane >> 2, t = lane & 3;
        int n = ng * 8 + g;
        int k0 = 2 * t;
        uint2 o;
        o.x = pack_h2(W0[(k0    )*HID + n], W0[(k0 + 1)*HID + n]);
        o.y = pack_h2(W0[(k0 + 8)*HID + n], W0[(k0 + 9)*HID + n]);
        g_W0f[idx] = o;
    } else if (idx < T0 + T1) {
        int i = idx - T0;
        int lane = i & 31, ng = (i >> 5) & 63, ks = i >> 11;
        int g = lane >> 2, t = lane & 3;
        int n = ng * 8 + g;
        int k0 = ks * 16 + 2 * t;
        uint2 o;
        o.x = pack_h2(W1[(k0    )*HID + n], W1[(k0 + 1)*HID + n]);
        o.y = pack_h2(W1[(k0 + 8)*HID + n], W1[(k0 + 9)*HID + n]);
        g_W1f[i] = o;
    } else if (idx < T0 + T1 + T2) {
        int j = idx - T0 - T1;
        int lane = j & 31, ng = (j >> 5) % 20, ks = j / (20 * 32);
        int g = lane >> 2, t = lane & 3;
        int n = ng * 8 + g;
        int k0 = ks * 16 + 2 * t;
        float v00 = (n < NOUT) ? W2[(k0    )*NOUT + n] : 0.0f;
        float v01 = (n < NOUT) ? W2[(k0 + 1)*NOUT + n] : 0.0f;
        float v10 = (n < NOUT) ? W2[(k0 + 8)*NOUT + n] : 0.0f;
        float v11 = (n < NOUT) ? W2[(k0 + 9)*NOUT + n] : 0.0f;
        uint2 o;
        o.x = pack_h2(v00, v01);
        o.y = pack_h2(v10, v11);
        g_W2f[j] = o;
    }
}

__device__ __forceinline__ void mma16816h(float* d, const uint32_t* a,
                                          uint32_t b0, uint32_t b1)
{
    asm volatile(
        "mma.sync.aligned.m16n8k16.row.col.f32.f16.f16.f32 "
        "{%0,%1,%2,%3}, {%4,%5,%6,%7}, {%8,%9}, {%0,%1,%2,%3};\n"
        : "+f"(d[0]), "+f"(d[1]), "+f"(d[2]), "+f"(d[3])
        : "r"(a[0]), "r"(a[1]), "r"(a[2]), "r"(a[3]),
          "r"(b0), "r"(b1));
}

__device__ __forceinline__ void ldsm4(uint32_t* r, uint32_t saddr)
{
    asm volatile("ldmatrix.sync.aligned.m8n8.x4.shared.b16 {%0,%1,%2,%3}, [%4];\n"
                 : "=r"(r[0]), "=r"(r[1]), "=r"(r[2]), "=r"(r[3])
                 : "r"(saddr));
}

__device__ __forceinline__ float ftanh(float x)
{
    float y;
    asm("tanh.approx.f32 %0, %1;" : "=f"(y) : "f"(x));
    return y;
}

__global__ __launch_bounds__(TH, 2)
void ptpd_mma_kernel(const float* __restrict__ pts,
                     const float* __restrict__ b0,
                     const float* __restrict__ b1, const float* __restrict__ b2,
                     float* __restrict__ out)
{
    extern __shared__ char sm[];
    float*  Xs  = (float*)(sm + XS_OFF);
    __half* Xh  = (__half*)(sm + XH_OFF);
    __half* Hh  = (__half*)(sm + HH_OFF);
    float*  netS = (float*)(sm + NET_OFF);   // overlays Hh after L2 MMAs

    const uint32_t smb = (uint32_t)__cvta_generic_to_shared(sm);
    const uint32_t xhS = smb + XH_OFF;
    const uint32_t hhS = smb + HH_OFF;

    const int tid  = threadIdx.x;
    const int lane = tid & 31;
    const int wid  = tid >> 5;
    const int g    = lane >> 2;
    const int t    = lane & 3;
    const long row0 = (long)blockIdx.x * TM;

    const int arow  = lane & 15;
    const int acol8 = (lane >> 4) << 3;

    // ---------------- X tile: fp32 + fp16 copy ----------------
    for (int i = tid; i < TM*NIN; i += TH) {
        float x = pts[row0*NIN + i];
        Xs[i] = x;
        int r = i >> 4, c = i & 15;
        Xh[r*XSTR + c] = __float2half_rn(x);
    }
    __syncthreads();

    // ---------------- layer 0 via MMA (K=16, single-term fp16) ----------------
    {
        float acc0[2][8][4];
        #pragma unroll
        for (int nt = 0; nt < 8; nt++) {
            int col = wid*64 + nt*8 + 2*t;
            float bv0 = b0[col], bv1 = b0[col + 1];
            #pragma unroll
            for (int mt = 0; mt < 2; mt++) {
                acc0[mt][nt][0] = bv0; acc0[mt][nt][1] = bv1;
                acc0[mt][nt][2] = bv0; acc0[mt][nt][3] = bv1;
            }
        }
        uint32_t xhf[2][4];
        #pragma unroll
        for (int mt = 0; mt < 2; mt++) {
            int ro = (mt*16 + arow)*XSTR + acol8;
            ldsm4(xhf[mt], xhS + ro*2);
        }
        const uint2* __restrict__ wp0 = g_W0f + (wid*8)*32 + lane;
        uint2 bv[8];
        #pragma unroll
        for (int nt = 0; nt < 8; nt++)
            bv[nt] = wp0[nt*32];
        #pragma unroll
        for (int nt = 0; nt < 8; nt++)
            #pragma unroll
            for (int mt = 0; mt < 2; mt++)
                mma16816h(acc0[mt][nt], xhf[mt], bv[nt].x, bv[nt].y);

        // tanh -> H0 (fp16)
        #pragma unroll
        for (int mt = 0; mt < 2; mt++)
            #pragma unroll
            for (int nt = 0; nt < 8; nt++) {
                int r   = mt*16 + g;
                int col = wid*64 + nt*8 + 2*t;
                *(__half2*)(Hh + r*HS + col) =
                    __floats2half2_rn(ftanh(acc0[mt][nt][0]), ftanh(acc0[mt][nt][1]));
                *(__half2*)(Hh + (r + 8)*HS + col) =
                    __floats2half2_rn(ftanh(acc0[mt][nt][2]), ftanh(acc0[mt][nt][3]));
            }
    }
    __syncthreads();

    // ====== layer 1: single-term fp16, rotating B prefetch ======
    {
        float acc1[2][8][4];
        #pragma unroll
        for (int nt = 0; nt < 8; nt++) {
            int col = wid*64 + nt*8 + 2*t;
            float bv0 = b1[col], bv1 = b1[col + 1];
            #pragma unroll
            for (int mt = 0; mt < 2; mt++) {
                acc1[mt][nt][0] = bv0; acc1[mt][nt][1] = bv1;
                acc1[mt][nt][2] = bv0; acc1[mt][nt][3] = bv1;
            }
        }

        const uint2* __restrict__ wp = g_W1f + (wid*8)*32 + lane;
        uint32_t a0 = hhS + (uint32_t)(arow*HS + acol8)*2;
        uint32_t a1 = a0 + 16*HS*2;

        // peel: load ks=0 fragments
        uint2 bv[8];
        #pragma unroll
        for (int nt = 0; nt < 8; nt++)
            bv[nt] = wp[nt*32];
        wp += 64*32;

        for (int ks = 0; ks < 32; ks++) {
            uint32_t ah[2][4];
            ldsm4(ah[0], a0);
            ldsm4(ah[1], a1);
            a0 += 32; a1 += 32;

            // MMA with bv[nt], then immediately reload bv[nt] for ks+1
            // (same registers; padded array makes the final loads in-bounds)
            #pragma unroll
            for (int nt = 0; nt < 8; nt++) {
                mma16816h(acc1[0][nt], ah[0], bv[nt].x, bv[nt].y);
                mma16816h(acc1[1][nt], ah[1], bv[nt].x, bv[nt].y);
                bv[nt] = wp[nt*32];
            }
            wp += 64*32;
        }

        __syncthreads();    // all warps done READING H0 before overwrite

        // tanh -> H1 (overwrites H0)
        #pragma unroll
        for (int mt = 0; mt < 2; mt++)
            #pragma unroll
            for (int nt = 0; nt < 8; nt++) {
                int r   = mt*16 + g;
                int col = wid*64 + nt*8 + 2*t;
                *(__half2*)(Hh + r*HS + col) =
                    __floats2half2_rn(ftanh(acc1[mt][nt][0]), ftanh(acc1[mt][nt][1]));
                *(__half2*)(Hh + (r + 8)*HS + col) =
                    __floats2half2_rn(ftanh(acc1[mt][nt][2]), ftanh(acc1[mt][nt][3]));
            }
    }
    __syncthreads();

    // ====== layer 2: single-term fp16, rotating B prefetch ======
    {
        const int wm = wid & 1;      // 16 rows each
        const int wn = wid >> 1;     // 40 cols (5 n-tiles)
        float acc2[5][4];
        #pragma unroll
        for (int nt = 0; nt < 5; nt++) {
            int col = wn*40 + nt*8 + 2*t;
            float bv0 = (col     < NOUT) ? b2[col]     : 0.0f;
            float bv1 = (col + 1 < NOUT) ? b2[col + 1] : 0.0f;
            acc2[nt][0] = bv0; acc2[nt][1] = bv1;
            acc2[nt][2] = bv0; acc2[nt][3] = bv1;
        }

        const uint2* __restrict__ wp2 = g_W2f + (wn*5)*32 + lane;
        uint32_t a0 = hhS + (uint32_t)((wm*16 + arow)*HS + acol8)*2;

        uint2 bv[5];
        #pragma unroll
        for (int nt = 0; nt < 5; nt++)
            bv[nt] = wp2[nt*32];
        wp2 += 20*32;

        for (int ks = 0; ks < 32; ks++) {
            uint32_t ah[4];
            ldsm4(ah, a0);
            a0 += 32;

            #pragma unroll
            for (int nt = 0; nt < 5; nt++) {
                mma16816h(acc2[nt], ah, bv[nt].x, bv[nt].y);
                bv[nt] = wp2[nt*32];
            }
            wp2 += 20*32;
        }

        __syncthreads();   // all warps done READING H1 -> netS overlay safe

        // net -> smem (overlays Hh)
        #pragma unroll
        for (int nt = 0; nt < 5; nt++) {
            int r   = wm*16 + g;
            int col = wn*40 + nt*8 + 2*t;
            if (col + 1 < NOUT) {
                netS[r*NETS + col]           = acc2[nt][0];
                netS[r*NETS + col + 1]       = acc2[nt][1];
                netS[(r + 8)*NETS + col]     = acc2[nt][2];
                netS[(r + 8)*NETS + col + 1] = acc2[nt][3];
            }
        }
    }
    __syncthreads();

    // ---------------- quadratic form ----------------
    if (tid < TM) {
        const float* nn = netS + tid*NETS;
        const float* xv = Xs + tid*NIN;
        float x[NIN], sx = 0.0f;
        #pragma unroll
        for (int i = 0; i < NIN; i++) { x[i] = xv[i]; sx = fmaf(x[i], x[i], sx); }
        float y[NIN];
        #pragma unroll
        for (int j = 0; j < NIN; j++) y[j] = 0.0f;
        int tt = 0;
        #pragma unroll
        for (int i = 0; i < NIN; i++) {
            #pragma unroll
            for (int j = 0; j <= i; j++) {
                y[j] = fmaf(nn[tt], x[i], y[j]);
                tt++;
            }
        }
        float v = 0.0f;
        #pragma unroll
        for (int j = 0; j < NIN; j++) v = fmaf(y[j], y[j], v);
        out[row0 + tid] = v + 1e-6f * sx;
    }
}

extern "C" void kernel_launch(void* const* d_in, const int* in_sizes, int n_in,
                              void* d_out, int out_size)
{
    const float* pts = (const float*)d_in[0];
    const float* W0  = (const float*)d_in[1];
    const float* b0  = (const float*)d_in[2];
    const float* W1  = (const float*)d_in[3];
    const float* b1  = (const float*)d_in[4];
    const float* W2  = (const float*)d_in[5];
    const float* b2  = (const float*)d_in[6];
    float* out = (float*)d_out;

    const int B = in_sizes[0] / NIN;

    cudaFuncSetAttribute(ptpd_mma_kernel,
                         cudaFuncAttributeMaxDynamicSharedMemorySize, SMEM_BYTES);

    const int prep_threads = 64*32 + 32*64*32 + 32*20*32;
    prep_weights<<<(prep_threads + 255)/256, 256>>>(W0, W1, W2);

    ptpd_mma_kernel<<<B/TM, TH, SMEM_BYTES>>>(pts, b0, b1, b2, out);
}

// round 16
// speedup vs baseline: 11.0375x; 1.0859x over previous
#include <cuda_runtime.h>
#include <cuda_fp16.h>
#include <stdint.h>

#define TH 256
#define TM 32
#define HID 512
#define NIN 16
#define NOUT 136
#define HS 520              // H row stride (fp16): conflict-free for ldmatrix
#define XSTR 24             // X row stride (fp16)
#define NETS 137

#define XS_OFF  0                        // 32*16*4 = 2048
#define XH_OFF  2048                     // 32*24*2 = 1536
#define HH_OFF  (XH_OFF + 1536)          // 3584
#define SMEM_BYTES (HH_OFF + 33280)      // 36864
#define NET_OFF HH_OFF                   // netS overlays Hh (free after L2 MMAs)

// pair-packed fp16 weight fragments:
// [ks][ngpair][lane] -> {ngA.b0, ngA.b1, ngB.b0, ngB.b1}
// +1 k-step padding: rotating prefetch reads (never uses) ks==32.
__device__ __align__(16) uint2 g_W0f[64 * 32];          // 16 KB (L0, unpaired)
__device__ __align__(16) uint4 g_W1f[33 * 32 * 32];     // 528 KB
__device__ __align__(16) uint4 g_W2f[33 * 12 * 32];     // 198 KB (N padded to 192)

__device__ __forceinline__ uint32_t pack_h2(float a, float b)
{
    __half2 p = __floats2half2_rn(a, b);
    return *(uint32_t*)&p;
}

__global__ void prep_weights(const float* __restrict__ W0,
                             const float* __restrict__ W1,
                             const float* __restrict__ W2)
{
    int idx = blockIdx.x * blockDim.x + threadIdx.x;
    const int T0 = 64 * 32;
    const int T1 = 32 * 32 * 32;    // (ks, ngpair, lane)
    const int T2 = 32 * 12 * 32;
    if (idx < T0) {
        int lane = idx & 31, ng = idx >> 5;
        int g = lane >> 2, t = lane & 3;
        int n = ng * 8 + g;
        int k0 = 2 * t;
        uint2 o;
        o.x = pack_h2(W0[(k0    )*HID + n], W0[(k0 + 1)*HID + n]);
        o.y = pack_h2(W0[(k0 + 8)*HID + n], W0[(k0 + 9)*HID + n]);
        g_W0f[idx] = o;
    } else if (idx < T0 + T1) {
        int i = idx - T0;
        int lane = i & 31, ngp = (i >> 5) & 31, ks = i >> 10;
        int g = lane >> 2, t = lane & 3;
        int n0 = (ngp * 2) * 8 + g;
        int n1 = n0 + 8;
        int k0 = ks * 16 + 2 * t;
        uint4 o;
        o.x = pack_h2(W1[(k0    )*HID + n0], W1[(k0 + 1)*HID + n0]);
        o.y = pack_h2(W1[(k0 + 8)*HID + n0], W1[(k0 + 9)*HID + n0]);
        o.z = pack_h2(W1[(k0    )*HID + n1], W1[(k0 + 1)*HID + n1]);
        o.w = pack_h2(W1[(k0 + 8)*HID + n1], W1[(k0 + 9)*HID + n1]);
        g_W1f[ks * (32*32) + ngp * 32 + lane] = o;
    } else if (idx < T0 + T1 + T2) {
        int j = idx - T0 - T1;
        int lane = j & 31, ngp = (j >> 5) % 12, ks = j / (12 * 32);
        int g = lane >> 2, t = lane & 3;
        int wn = ngp / 3, jj = ngp % 3;
        int nt0 = 2 * jj, nt1 = 2 * jj + 1;
        int n0 = wn * 40 + nt0 * 8 + g;            // nt0 <= 4 always
        int n1 = (nt1 < 5) ? (wn * 40 + nt1 * 8 + g) : NOUT;  // pad -> zero
        int k0 = ks * 16 + 2 * t;
        float a00 = (n0 < NOUT) ? W2[(k0    )*NOUT + n0] : 0.0f;
        float a01 = (n0 < NOUT) ? W2[(k0 + 1)*NOUT + n0] : 0.0f;
        float a10 = (n0 < NOUT) ? W2[(k0 + 8)*NOUT + n0] : 0.0f;
        float a11 = (n0 < NOUT) ? W2[(k0 + 9)*NOUT + n0] : 0.0f;
        float c00 = (n1 < NOUT) ? W2[(k0    )*NOUT + n1] : 0.0f;
        float c01 = (n1 < NOUT) ? W2[(k0 + 1)*NOUT + n1] : 0.0f;
        float c10 = (n1 < NOUT) ? W2[(k0 + 8)*NOUT + n1] : 0.0f;
        float c11 = (n1 < NOUT) ? W2[(k0 + 9)*NOUT + n1] : 0.0f;
        uint4 o;
        o.x = pack_h2(a00, a01);
        o.y = pack_h2(a10, a11);
        o.z = pack_h2(c00, c01);
        o.w = pack_h2(c10, c11);
        g_W2f[ks * (12*32) + ngp * 32 + lane] = o;
    }
}

__device__ __forceinline__ void mma16816h(float* d, const uint32_t* a,
                                          uint32_t b0, uint32_t b1)
{
    asm volatile(
        "mma.sync.aligned.m16n8k16.row.col.f32.f16.f16.f32 "
        "{%0,%1,%2,%3}, {%4,%5,%6,%7}, {%8,%9}, {%0,%1,%2,%3};\n"
        : "+f"(d[0]), "+f"(d[1]), "+f"(d[2]), "+f"(d[3])
        : "r"(a[0]), "r"(a[1]), "r"(a[2]), "r"(a[3]),
          "r"(b0), "r"(b1));
}

__device__ __forceinline__ void ldsm4(uint32_t* r, uint32_t saddr)
{
    asm volatile("ldmatrix.sync.aligned.m8n8.x4.shared.b16 {%0,%1,%2,%3}, [%4];\n"
                 : "=r"(r[0]), "=r"(r[1]), "=r"(r[2]), "=r"(r[3])
                 : "r"(saddr));
}

__device__ __forceinline__ float ftanh(float x)
{
    float y;
    asm("tanh.approx.f32 %0, %1;" : "=f"(y) : "f"(x));
    return y;
}

__global__ __launch_bounds__(TH, 2)
void ptpd_mma_kernel(const float* __restrict__ pts,
                     const float* __restrict__ b0,
                     const float* __restrict__ b1, const float* __restrict__ b2,
                     float* __restrict__ out)
{
    extern __shared__ char sm[];
    float*  Xs  = (float*)(sm + XS_OFF);
    __half* Xh  = (__half*)(sm + XH_OFF);
    __half* Hh  = (__half*)(sm + HH_OFF);
    float*  netS = (float*)(sm + NET_OFF);   // overlays Hh after L2 MMAs

    const uint32_t smb = (uint32_t)__cvta_generic_to_shared(sm);
    const uint32_t xhS = smb + XH_OFF;
    const uint32_t hhS = smb + HH_OFF;

    const int tid  = threadIdx.x;
    const int lane = tid & 31;
    const int wid  = tid >> 5;
    const int g    = lane >> 2;
    const int t    = lane & 3;
    const long row0 = (long)blockIdx.x * TM;

    const int arow  = lane & 15;
    const int acol8 = (lane >> 4) << 3;

    // ---------------- X tile: fp32 + fp16 copy ----------------
    for (int i = tid; i < TM*NIN; i += TH) {
        float x = pts[row0*NIN + i];
        Xs[i] = x;
        int r = i >> 4, c = i & 15;
        Xh[r*XSTR + c] = __float2half_rn(x);
    }
    __syncthreads();

    // ---------------- layer 0 via MMA (K=16, single-term fp16) ----------------
    {
        float acc0[2][8][4];
        #pragma unroll
        for (int nt = 0; nt < 8; nt++) {
            int col = wid*64 + nt*8 + 2*t;
            float bv0 = b0[col], bv1 = b0[col + 1];
            #pragma unroll
            for (int mt = 0; mt < 2; mt++) {
                acc0[mt][nt][0] = bv0; acc0[mt][nt][1] = bv1;
                acc0[mt][nt][2] = bv0; acc0[mt][nt][3] = bv1;
            }
        }
        uint32_t xhf[2][4];
        #pragma unroll
        for (int mt = 0; mt < 2; mt++) {
            int ro = (mt*16 + arow)*XSTR + acol8;
            ldsm4(xhf[mt], xhS + ro*2);
        }
        const uint2* __restrict__ wp0 = g_W0f + (wid*8)*32 + lane;
        uint2 bv[8];
        #pragma unroll
        for (int nt = 0; nt < 8; nt++)
            bv[nt] = wp0[nt*32];
        #pragma unroll
        for (int nt = 0; nt < 8; nt++)
            #pragma unroll
            for (int mt = 0; mt < 2; mt++)
                mma16816h(acc0[mt][nt], xhf[mt], bv[nt].x, bv[nt].y);

        // tanh -> H0 (fp16)
        #pragma unroll
        for (int mt = 0; mt < 2; mt++)
            #pragma unroll
            for (int nt = 0; nt < 8; nt++) {
                int r   = mt*16 + g;
                int col = wid*64 + nt*8 + 2*t;
                *(__half2*)(Hh + r*HS + col) =
                    __floats2half2_rn(ftanh(acc0[mt][nt][0]), ftanh(acc0[mt][nt][1]));
                *(__half2*)(Hh + (r + 8)*HS + col) =
                    __floats2half2_rn(ftanh(acc0[mt][nt][2]), ftanh(acc0[mt][nt][3]));
            }
    }
    __syncthreads();

    // ====== layer 1: single-term fp16, pair-packed B, rotating prefetch ======
    {
        float acc1[2][8][4];
        #pragma unroll
        for (int nt = 0; nt < 8; nt++) {
            int col = wid*64 + nt*8 + 2*t;
            float bv0 = b1[col], bv1 = b1[col + 1];
            #pragma unroll
            for (int mt = 0; mt < 2; mt++) {
                acc1[mt][nt][0] = bv0; acc1[mt][nt][1] = bv1;
                acc1[mt][nt][2] = bv0; acc1[mt][nt][3] = bv1;
            }
        }

        const uint4* __restrict__ wp = g_W1f + (wid*4)*32 + lane;
        uint32_t a0 = hhS + (uint32_t)(arow*HS + acol8)*2;
        uint32_t a1 = a0 + 16*HS*2;

        // peel: ks=0 fragments (4 x LDG.128)
        uint4 bv[4];
        #pragma unroll
        for (int j = 0; j < 4; j++)
            bv[j] = wp[j*32];
        wp += 32*32;

        #pragma unroll 2
        for (int ks = 0; ks < 32; ks++) {
            uint32_t ah[2][4];
            ldsm4(ah[0], a0);
            ldsm4(ah[1], a1);
            a0 += 32; a1 += 32;

            // use pair j (n-tiles 2j, 2j+1), then reload for ks+1
            #pragma unroll
            for (int j = 0; j < 4; j++) {
                mma16816h(acc1[0][2*j],     ah[0], bv[j].x, bv[j].y);
                mma16816h(acc1[1][2*j],     ah[1], bv[j].x, bv[j].y);
                mma16816h(acc1[0][2*j + 1], ah[0], bv[j].z, bv[j].w);
                mma16816h(acc1[1][2*j + 1], ah[1], bv[j].z, bv[j].w);
                bv[j] = wp[j*32];
            }
            wp += 32*32;
        }

        __syncthreads();    // all warps done READING H0 before overwrite

        // tanh -> H1 (overwrites H0)
        #pragma unroll
        for (int mt = 0; mt < 2; mt++)
            #pragma unroll
            for (int nt = 0; nt < 8; nt++) {
                int r   = mt*16 + g;
                int col = wid*64 + nt*8 + 2*t;
                *(__half2*)(Hh + r*HS + col) =
                    __floats2half2_rn(ftanh(acc1[mt][nt][0]), ftanh(acc1[mt][nt][1]));
                *(__half2*)(Hh + (r + 8)*HS + col) =
                    __floats2half2_rn(ftanh(acc1[mt][nt][2]), ftanh(acc1[mt][nt][3]));
            }
    }
    __syncthreads();

    // ====== layer 2: single-term fp16, pair-packed B, rotating prefetch ======
    {
        const int wm = wid & 1;      // 16 rows each
        const int wn = wid >> 1;     // 40 cols (5 n-tiles)
        float acc2[5][4];
        #pragma unroll
        for (int nt = 0; nt < 5; nt++) {
            int col = wn*40 + nt*8 + 2*t;
            float bv0 = (col     < NOUT) ? b2[col]     : 0.0f;
            float bv1 = (col + 1 < NOUT) ? b2[col + 1] : 0.0f;
            acc2[nt][0] = bv0; acc2[nt][1] = bv1;
            acc2[nt][2] = bv0; acc2[nt][3] = bv1;
        }

        const uint4* __restrict__ wp2 = g_W2f + (wn*3)*32 + lane;
        uint32_t a0 = hhS + (uint32_t)((wm*16 + arow)*HS + acol8)*2;

        uint4 bv[3];
        #pragma unroll
        for (int j = 0; j < 3; j++)
            bv[j] = wp2[j*32];
        wp2 += 12*32;

        for (int ks = 0; ks < 32; ks++) {
            uint32_t ah[4];
            ldsm4(ah, a0);
            a0 += 32;

            mma16816h(acc2[0], ah, bv[0].x, bv[0].y);
            mma16816h(acc2[1], ah, bv[0].z, bv[0].w);
            bv[0] = wp2[0*32];
            mma16816h(acc2[2], ah, bv[1].x, bv[1].y);
            mma16816h(acc2[3], ah, bv[1].z, bv[1].w);
            bv[1] = wp2[1*32];
            mma16816h(acc2[4], ah, bv[2].x, bv[2].y);
            bv[2] = wp2[2*32];
            wp2 += 12*32;
        }

        __syncthreads();   // all warps done READING H1 -> netS overlay safe

        // net -> smem (overlays Hh)
        #pragma unroll
        for (int nt = 0; nt < 5; nt++) {
            int r   = wm*16 + g;
            int col = wn*40 + nt*8 + 2*t;
            if (col + 1 < NOUT) {
                netS[r*NETS + col]           = acc2[nt][0];
                netS[r*NETS + col + 1]       = acc2[nt][1];
                netS[(r + 8)*NETS + col]     = acc2[nt][2];
                netS[(r + 8)*NETS + col + 1] = acc2[nt][3];
            }
        }
    }
    __syncthreads();

    // ---------------- quadratic form ----------------
    if (tid < TM) {
        const float* nn = netS + tid*NETS;
        const float* xv = Xs + tid*NIN;
        float x[NIN], sx = 0.0f;
        #pragma unroll
        for (int i = 0; i < NIN; i++) { x[i] = xv[i]; sx = fmaf(x[i], x[i], sx); }
        float y[NIN];
        #pragma unroll
        for (int j = 0; j < NIN; j++) y[j] = 0.0f;
        int tt = 0;
        #pragma unroll
        for (int i = 0; i < NIN; i++) {
            #pragma unroll
            for (int j = 0; j <= i; j++) {
                y[j] = fmaf(nn[tt], x[i], y[j]);
                tt++;
            }
        }
        float v = 0.0f;
        #pragma unroll
        for (int j = 0; j < NIN; j++) v = fmaf(y[j], y[j], v);
        out[row0 + tid] = v + 1e-6f * sx;
    }
}

extern "C" void kernel_launch(void* const* d_in, const int* in_sizes, int n_in,
                              void* d_out, int out_size)
{
    const float* pts = (const float*)d_in[0];
    const float* W0  = (const float*)d_in[1];
    const float* b0  = (const float*)d_in[2];
    const float* W1  = (const float*)d_in[3];
    const float* b1  = (const float*)d_in[4];
    const float* W2  = (const float*)d_in[5];
    const float* b2  = (const float*)d_in[6];
    float* out = (float*)d_out;

    const int B = in_sizes[0] / NIN;

    cudaFuncSetAttribute(ptpd_mma_kernel,
                         cudaFuncAttributeMaxDynamicSharedMemorySize, SMEM_BYTES);

    const int prep_threads = 64*32 + 32*32*32 + 32*12*32;
    prep_weights<<<(prep_threads + 255)/256, 256>>>(W0, W1, W2);

    ptpd_mma_kernel<<<B/TM, TH, SMEM_BYTES>>>(pts, b0, b1, b2, out);
}